// round 1
// baseline (speedup 1.0000x reference)
#include <cuda_runtime.h>
#include <math.h>

// Problem constants
#define NB   4
#define SEQ  4096
#define EMB  512
#define NTOK (NB * SEQ)   // 16384

// ---------------------------------------------------------------------------
// Device scratch (allocation-free rule: __device__ globals)
// ---------------------------------------------------------------------------
__device__ float g_Qp[(size_t)NTOK * EMB];                 // 32 MB
__device__ float g_Kp[(size_t)NTOK * EMB];                 // 32 MB
__device__ float g_Vp[(size_t)NTOK * EMB];                 // 32 MB
__device__ float g_AO[(size_t)NTOK * EMB];                 // 32 MB
__device__ float g_E [(size_t)NB * SEQ * SEQ];             // 1 GB (energy / attn, in place)

// ---------------------------------------------------------------------------
// Classic 128x128x8 double-buffered SGEMM, 256 threads, 8x8 per-thread tile.
// BLAYOUT=0: C = A[M,K] * B[N,K]^T   (NT; both K-contiguous)
// BLAYOUT=1: C = A[M,K] * B[K,N]     (NN; B N-contiguous)
// All of M, N multiples of 128; K multiple of 8. No bounds checks needed.
// ---------------------------------------------------------------------------
template <int BLAYOUT, bool ADD_BIAS>
__global__ void __launch_bounds__(256, 2)
sgemm_kernel(const float* __restrict__ Ag, const float* __restrict__ Bg,
             float* __restrict__ Cg, const float* __restrict__ bias,
             int M, int N, int K,
             long long sA, long long sB, long long sC)
{
    __shared__ float As[2][8][128];
    __shared__ float Bs[2][8][128];

    const int tid = threadIdx.x;
    const float* A = Ag + (long long)blockIdx.z * sA;
    const float* B = Bg + (long long)blockIdx.z * sB;
    float*       C = Cg + (long long)blockIdx.z * sC;

    const int bm = blockIdx.y * 128;
    const int bn = blockIdx.x * 128;

    // global->smem load mapping
    const int ld_row = tid >> 1;          // 0..127 (m index for A; n index for NT B)
    const int ld_k   = (tid & 1) << 2;    // 0 or 4
    const int nn_k   = tid >> 5;          // 0..7   (k row for NN B)
    const int nn_n   = (tid & 31) << 2;   // 0..124 (n col for NN B)

    const float* Aptr = A + (long long)(bm + ld_row) * K + ld_k;
    const float* Bptr = (BLAYOUT == 0)
        ? (B + (long long)(bn + ld_row) * K + ld_k)
        : (B + (long long)nn_k * N + bn + nn_n);

    // fetch tile 0
    float4 ra = *(const float4*)Aptr;
    float4 rb = *(const float4*)Bptr;

    // stage tile 0 into buffer 0
    As[0][ld_k + 0][ld_row] = ra.x;
    As[0][ld_k + 1][ld_row] = ra.y;
    As[0][ld_k + 2][ld_row] = ra.z;
    As[0][ld_k + 3][ld_row] = ra.w;
    if (BLAYOUT == 0) {
        Bs[0][ld_k + 0][ld_row] = rb.x;
        Bs[0][ld_k + 1][ld_row] = rb.y;
        Bs[0][ld_k + 2][ld_row] = rb.z;
        Bs[0][ld_k + 3][ld_row] = rb.w;
    } else {
        *(float4*)&Bs[0][nn_k][nn_n] = rb;
    }
    __syncthreads();

    const int tx = (tid & 15) << 3;  // 0..120
    const int ty = (tid >> 4) << 3;  // 0..120

    float acc[8][8] = {};

    const int nT = K >> 3;
#pragma unroll 1
    for (int t = 0; t < nT; ++t) {
        const int cur = t & 1;
        if (t + 1 < nT) {
            const int k0 = (t + 1) << 3;
            ra = *(const float4*)(Aptr + k0);
            rb = (BLAYOUT == 0)
               ? *(const float4*)(Bptr + k0)
               : *(const float4*)(Bptr + (long long)k0 * N);
        }
#pragma unroll
        for (int kk = 0; kk < 8; ++kk) {
            float a0[8], b0[8];
            *(float4*)&a0[0] = *(const float4*)&As[cur][kk][ty];
            *(float4*)&a0[4] = *(const float4*)&As[cur][kk][ty + 4];
            *(float4*)&b0[0] = *(const float4*)&Bs[cur][kk][tx];
            *(float4*)&b0[4] = *(const float4*)&Bs[cur][kk][tx + 4];
#pragma unroll
            for (int i = 0; i < 8; ++i)
#pragma unroll
                for (int j = 0; j < 8; ++j)
                    acc[i][j] += a0[i] * b0[j];
        }
        if (t + 1 < nT) {
            const int nxt = cur ^ 1;
            As[nxt][ld_k + 0][ld_row] = ra.x;
            As[nxt][ld_k + 1][ld_row] = ra.y;
            As[nxt][ld_k + 2][ld_row] = ra.z;
            As[nxt][ld_k + 3][ld_row] = ra.w;
            if (BLAYOUT == 0) {
                Bs[nxt][ld_k + 0][ld_row] = rb.x;
                Bs[nxt][ld_k + 1][ld_row] = rb.y;
                Bs[nxt][ld_k + 2][ld_row] = rb.z;
                Bs[nxt][ld_k + 3][ld_row] = rb.w;
            } else {
                *(float4*)&Bs[nxt][nn_k][nn_n] = rb;
            }
            __syncthreads();
        }
    }

    // epilogue
    float bv[8];
    if (ADD_BIAS) {
        *(float4*)&bv[0] = *(const float4*)(bias + bn + tx);
        *(float4*)&bv[4] = *(const float4*)(bias + bn + tx + 4);
    }
#pragma unroll
    for (int i = 0; i < 8; ++i) {
        float* crow = C + (long long)(bm + ty + i) * N + bn + tx;
#pragma unroll
        for (int j = 0; j < 8; j += 4) {
            float4 o;
            o.x = acc[i][j + 0];
            o.y = acc[i][j + 1];
            o.z = acc[i][j + 2];
            o.w = acc[i][j + 3];
            if (ADD_BIAS) {
                o.x += bv[j + 0]; o.y += bv[j + 1];
                o.z += bv[j + 2]; o.w += bv[j + 3];
            }
            *(float4*)(crow + j) = o;
        }
    }
}

// ---------------------------------------------------------------------------
// Fused scale + mask + softmax over each row of the energy matrix (in place).
// One CTA (256 threads) per row of 4096; row values held in registers.
// Matches reference: energy = where(mask==0, -1e20, energy); softmax(energy*scale)
// ---------------------------------------------------------------------------
__global__ void softmax_mask_kernel(float* __restrict__ E, const int* __restrict__ mask)
{
    const long long row = blockIdx.x;            // 0 .. NB*SEQ-1
    float* e = E + row * (long long)SEQ;
    const int* mr = mask + row * (long long)SEQ;
    const int tid = threadIdx.x;
    const float scale = 0.044194173824159216f;   // 1/sqrt(512)

    float v[16];
    float lmax = -3.0e38f;
#pragma unroll
    for (int i = 0; i < 16; ++i) {
        const int idx = tid + (i << 8);
        float x = e[idx];
        x = (mr[idx] == 0) ? -1.0e20f : x;
        x *= scale;
        v[i] = x;
        lmax = fmaxf(lmax, x);
    }

    __shared__ float red[8];
#pragma unroll
    for (int o = 16; o > 0; o >>= 1)
        lmax = fmaxf(lmax, __shfl_xor_sync(0xffffffffu, lmax, o));
    if ((tid & 31) == 0) red[tid >> 5] = lmax;
    __syncthreads();
    float rowmax = red[0];
#pragma unroll
    for (int w = 1; w < 8; ++w) rowmax = fmaxf(rowmax, red[w]);
    __syncthreads();

    float lsum = 0.f;
#pragma unroll
    for (int i = 0; i < 16; ++i) {
        v[i] = __expf(v[i] - rowmax);
        lsum += v[i];
    }
#pragma unroll
    for (int o = 16; o > 0; o >>= 1)
        lsum += __shfl_xor_sync(0xffffffffu, lsum, o);
    if ((tid & 31) == 0) red[tid >> 5] = lsum;
    __syncthreads();
    float rowsum = 0.f;
#pragma unroll
    for (int w = 0; w < 8; ++w) rowsum += red[w];
    const float inv = 1.0f / rowsum;
#pragma unroll
    for (int i = 0; i < 16; ++i)
        e[tid + (i << 8)] = v[i] * inv;
}

// ---------------------------------------------------------------------------
// Launch
// ---------------------------------------------------------------------------
extern "C" void kernel_launch(void* const* d_in, const int* in_sizes, int n_in,
                              void* d_out, int out_size)
{
    (void)in_sizes; (void)n_in; (void)out_size;

    const float* values = (const float*)d_in[0];  // [4,1,4096,512]
    const float* keys   = (const float*)d_in[1];
    const float* query  = (const float*)d_in[2];
    const int*   mask   = (const int*)  d_in[3];  // [4,1,4096,4096]
    const float* Wv     = (const float*)d_in[4];  // [512,512]
    const float* Wk     = (const float*)d_in[5];
    const float* Wq     = (const float*)d_in[6];
    const float* Wo     = (const float*)d_in[7];
    const float* bo     = (const float*)d_in[8];  // [512]
    float* out = (float*)d_out;                   // [4,4096,512]

    float *Qp, *Kp, *Vp, *AO, *E;
    cudaGetSymbolAddress((void**)&Qp, g_Qp);
    cudaGetSymbolAddress((void**)&Kp, g_Kp);
    cudaGetSymbolAddress((void**)&Vp, g_Vp);
    cudaGetSymbolAddress((void**)&AO, g_AO);
    cudaGetSymbolAddress((void**)&E,  g_E);

    const dim3 blk(256);

    // 1) Projections: [16384,512] = X[16384,512] @ W[512,512]^T   (NT)
    const dim3 gproj(EMB / 128, NTOK / 128, 1);
    sgemm_kernel<0, false><<<gproj, blk>>>(values, Wv, Vp, nullptr, NTOK, EMB, EMB, 0, 0, 0);
    sgemm_kernel<0, false><<<gproj, blk>>>(keys,   Wk, Kp, nullptr, NTOK, EMB, EMB, 0, 0, 0);
    sgemm_kernel<0, false><<<gproj, blk>>>(query,  Wq, Qp, nullptr, NTOK, EMB, EMB, 0, 0, 0);

    // 2) Energy: per-batch [4096,4096] = Qp @ Kp^T   (NT, batched)
    const long long sQK = (long long)SEQ * EMB;
    const long long sE  = (long long)SEQ * SEQ;
    const dim3 ge(SEQ / 128, SEQ / 128, NB);
    sgemm_kernel<0, false><<<ge, blk>>>(Qp, Kp, E, nullptr, SEQ, SEQ, EMB, sQK, sQK, sE);

    // 3) Mask + scale + softmax (in place on E)
    softmax_mask_kernel<<<NB * SEQ, 256>>>(E, mask);

    // 4) attn @ V: per-batch [4096,512] = E[4096,4096] @ Vp[4096,512]   (NN, batched)
    const dim3 gav(EMB / 128, SEQ / 128, NB);
    sgemm_kernel<1, false><<<gav, blk>>>(E, Vp, AO, nullptr, SEQ, EMB, SEQ, sE, sQK, sQK);

    // 5) Output projection + bias: [16384,512] = AO @ Wo^T + bo   (NT)
    sgemm_kernel<0, true><<<gproj, blk>>>(AO, Wo, out, bo, NTOK, EMB, EMB, 0, 0, 0);
}

// round 3
// speedup vs baseline: 2.8072x; 2.8072x over previous
#include <cuda_runtime.h>
#include <cuda_fp16.h>
#include <cstdint>

#define NB   4
#define SEQ  4096
#define EMB  512
#define NTOK (NB * SEQ)   // 16384

// ---------------------------------------------------------------------------
// Device scratch (allocation-free rule)
// ---------------------------------------------------------------------------
__device__ __half g_vh[(size_t)NTOK * EMB], g_vl[(size_t)NTOK * EMB];
__device__ __half g_kh[(size_t)NTOK * EMB], g_kl[(size_t)NTOK * EMB];
__device__ __half g_qh[(size_t)NTOK * EMB], g_ql[(size_t)NTOK * EMB];
__device__ __half g_Wvh[EMB * EMB], g_Wvl[EMB * EMB];
__device__ __half g_Wkh[EMB * EMB], g_Wkl[EMB * EMB];
__device__ __half g_Wqh[EMB * EMB], g_Wql[EMB * EMB];
__device__ __half g_Woh[EMB * EMB], g_Wol[EMB * EMB];
__device__ __half g_Qph[(size_t)NTOK * EMB], g_Qpl[(size_t)NTOK * EMB];
__device__ __half g_Kph[(size_t)NTOK * EMB], g_Kpl[(size_t)NTOK * EMB];
__device__ __half g_VTh[(size_t)NTOK * EMB], g_VTl[(size_t)NTOK * EMB]; // [b][d][l]
__device__ float  g_E  [(size_t)NB * SEQ * SEQ];                        // 268 MB
__device__ __half g_Ph [(size_t)NB * SEQ * SEQ], g_Pl[(size_t)NB * SEQ * SEQ];
__device__ __half g_AOh[(size_t)NTOK * EMB], g_AOl[(size_t)NTOK * EMB];

// ---------------------------------------------------------------------------
// helpers
// ---------------------------------------------------------------------------
__device__ __forceinline__ uint32_t smem_u32_of(const void* p) {
    uint32_t a;
    asm("{ .reg .u64 t; cvta.to.shared.u64 t, %1; cvt.u32.u64 %0, t; }" : "=r"(a) : "l"(p));
    return a;
}

__device__ __forceinline__ void ldsm4(uint32_t* r, uint32_t addr) {
    asm volatile("ldmatrix.sync.aligned.m8n8.x4.shared.b16 {%0,%1,%2,%3}, [%4];"
                 : "=r"(r[0]), "=r"(r[1]), "=r"(r[2]), "=r"(r[3]) : "r"(addr));
}

__device__ __forceinline__ void mma16816(float* c, const uint32_t* a, const uint32_t* b) {
    asm volatile(
        "mma.sync.aligned.m16n8k16.row.col.f32.f16.f16.f32 "
        "{%0,%1,%2,%3}, {%4,%5,%6,%7}, {%8,%9}, {%0,%1,%2,%3};"
        : "+f"(c[0]), "+f"(c[1]), "+f"(c[2]), "+f"(c[3])
        : "r"(a[0]), "r"(a[1]), "r"(a[2]), "r"(a[3]), "r"(b[0]), "r"(b[1]));
}

#define CP_ASYNC16(dst, src) \
    asm volatile("cp.async.cg.shared.global [%0], [%1], 16;" :: "r"(dst), "l"(src))
#define CP_COMMIT() asm volatile("cp.async.commit_group;")
#define CP_WAIT(n)  asm volatile("cp.async.wait_group %0;" :: "n"(n))

__device__ __forceinline__ uint32_t swz(uint32_t off) {
    return off ^ ((off >> 3) & 0x70);
}

__device__ __forceinline__ uint32_t packh2(__half a, __half b) {
    __half2 h = __halves2half2(a, b);
    return *(uint32_t*)&h;
}

// ---------------------------------------------------------------------------
// fp32 -> (hi, lo) fp16 split conversion
// ---------------------------------------------------------------------------
__global__ void cvt_hilo(const float4* __restrict__ x, uint2* __restrict__ h,
                         uint2* __restrict__ l, int n4)
{
    int i = blockIdx.x * 256 + threadIdx.x;
    if (i >= n4) return;
    float4 v = x[i];
    __half h0 = __float2half(v.x), h1 = __float2half(v.y);
    __half h2 = __float2half(v.z), h3 = __float2half(v.w);
    __half l0 = __float2half(v.x - __half2float(h0));
    __half l1 = __float2half(v.y - __half2float(h1));
    __half l2 = __float2half(v.z - __half2float(h2));
    __half l3 = __float2half(v.w - __half2float(h3));
    h[i] = make_uint2(packh2(h0, h1), packh2(h2, h3));
    l[i] = make_uint2(packh2(l0, l1), packh2(l2, l3));
}

// ---------------------------------------------------------------------------
// HMMA GEMM: C[128,128 tile] = A[M,K] @ B[N,K]^T with 3-term fp16 split
// (AhBh + AhBl + AlBh), fp32 accum.  K-contiguous A and B.
// EPI: 0 = fp32 C; 1 = hi/lo fp16 row-major; 2 = hi/lo fp16 transposed;
//      3 = fp32 + bias.
// ---------------------------------------------------------------------------
#define STAGES 3
#define STAGE_BYTES 65536          // 4 tiles * 128 rows * 128B
#define TILE_BYTES  16384

template <int EPI>
__global__ void __launch_bounds__(256, 1)
mma_gemm(const __half* __restrict__ Ah, const __half* __restrict__ Al,
         const __half* __restrict__ Bh, const __half* __restrict__ Bl,
         float* __restrict__ Cf, __half* __restrict__ Coh,
         __half* __restrict__ Col, const float* __restrict__ bias,
         int K, int ldC, long long sA, long long sB, long long sC)
{
    extern __shared__ __align__(1024) char smem[];
    const uint32_t smem_base = smem_u32_of(smem);

    const int tid = threadIdx.x;
    const int lane = tid & 31;
    const int w = tid >> 5;
    const int wm = w >> 2;          // 0..1
    const int wn = w & 3;           // 0..3
    const int z = blockIdx.z;
    const int bm = blockIdx.y * 128;
    const int bn = blockIdx.x * 128;

    const __half* gt0 = Ah + (long long)z * sA + (long long)bm * K;
    const __half* gt1 = Al + (long long)z * sA + (long long)bm * K;
    const __half* gt2 = Bh + (long long)z * sB + (long long)bn * K;
    const __half* gt3 = Bl + (long long)z * sB + (long long)bn * K;

    const int ld_row = tid >> 3;        // 0..31 (base row; +32 per i)
    const int ld_u   = tid & 7;         // 16B unit within 128B row

    auto load_chunk = [&](int c) {
        const int s = c % STAGES;
        const long long koff = (long long)c * 64;
        const uint32_t sbase = smem_base + s * STAGE_BYTES;
        const __half* gp[4] = { gt0 + koff, gt1 + koff, gt2 + koff, gt3 + koff };
#pragma unroll
        for (int t = 0; t < 4; ++t) {
            const uint32_t tb = sbase + t * TILE_BYTES;
#pragma unroll
            for (int i = 0; i < 4; ++i) {
                const int row = ld_row + i * 32;
                const void* g = gp[t] + (long long)row * K + ld_u * 8;
                const uint32_t dst = tb + swz((uint32_t)(row * 128 + ld_u * 16));
                CP_ASYNC16(dst, g);
            }
        }
        CP_COMMIT();
    };

    float acc[4][4][4] = {};

    const int nCh = K >> 6;
#pragma unroll 1
    for (int c = 0; c < STAGES; ++c) load_chunk(c);   // K >= 512 so nCh >= 8

#pragma unroll 1
    for (int c = 0; c < nCh; ++c) {
        const int s = c % STAGES;
        CP_WAIT(STAGES - 1);
        __syncthreads();

        const uint32_t sbase = smem_base + s * STAGE_BYTES;
#pragma unroll
        for (int ks = 0; ks < 4; ++ks) {
            uint32_t aH[4][4], aL[4][4], bH[4][2], bL[4][2];
#pragma unroll
            for (int mf = 0; mf < 4; ++mf) {
                const int r = wm * 64 + mf * 16 + (lane & 15);
                const uint32_t kb = ks * 32 + ((lane >> 4) << 4);
                const uint32_t off = swz((uint32_t)(r * 128 + kb));
                ldsm4(aH[mf], sbase + off);
                ldsm4(aL[mf], sbase + TILE_BYTES + off);
            }
#pragma unroll
            for (int nh = 0; nh < 2; ++nh) {
                const int n = wn * 32 + nh * 16 + (lane & 7) + ((lane >> 4) << 3);
                const uint32_t kb = ks * 32 + (((lane >> 3) & 1) << 4);
                const uint32_t off = swz((uint32_t)(n * 128 + kb));
                uint32_t r4[4];
                ldsm4(r4, sbase + 2 * TILE_BYTES + off);
                bH[2 * nh][0] = r4[0]; bH[2 * nh][1] = r4[1];
                bH[2 * nh + 1][0] = r4[2]; bH[2 * nh + 1][1] = r4[3];
                ldsm4(r4, sbase + 3 * TILE_BYTES + off);
                bL[2 * nh][0] = r4[0]; bL[2 * nh][1] = r4[1];
                bL[2 * nh + 1][0] = r4[2]; bL[2 * nh + 1][1] = r4[3];
            }
#pragma unroll
            for (int mf = 0; mf < 4; ++mf)
#pragma unroll
                for (int nf = 0; nf < 4; ++nf) {
                    mma16816(acc[mf][nf], aH[mf], bH[nf]);
                    mma16816(acc[mf][nf], aH[mf], bL[nf]);
                    mma16816(acc[mf][nf], aL[mf], bH[nf]);
                }
        }

        __syncthreads();
        if (c + STAGES < nCh) load_chunk(c + STAGES);
    }

    // ---- epilogue ----
    const int g = lane >> 2, tig = lane & 3;
#pragma unroll
    for (int mf = 0; mf < 4; ++mf) {
#pragma unroll
        for (int h2 = 0; h2 < 2; ++h2) {
            const int row = bm + wm * 64 + mf * 16 + g + h2 * 8;
#pragma unroll
            for (int nf = 0; nf < 4; ++nf) {
                const int col = bn + wn * 32 + nf * 8 + 2 * tig;
                const float x0 = acc[mf][nf][h2 * 2 + 0];
                const float x1 = acc[mf][nf][h2 * 2 + 1];
                if (EPI == 0) {
                    float2 o = make_float2(x0, x1);
                    *(float2*)(Cf + (long long)z * sC + (long long)row * ldC + col) = o;
                } else if (EPI == 3) {
                    float2 o = make_float2(x0 + bias[col], x1 + bias[col + 1]);
                    *(float2*)(Cf + (long long)z * sC + (long long)row * ldC + col) = o;
                } else if (EPI == 1) {
                    const long long base = (long long)z * sC + (long long)row * ldC + col;
                    __half hh0 = __float2half(x0), hh1 = __float2half(x1);
                    __half ll0 = __float2half(x0 - __half2float(hh0));
                    __half ll1 = __float2half(x1 - __half2float(hh1));
                    *(uint32_t*)(Coh + base) = packh2(hh0, hh1);
                    *(uint32_t*)(Col + base) = packh2(ll0, ll1);
                } else {  // EPI == 2: transposed, dest [b][d=col][l=row%4096]
                    const int b = row >> 12, l = row & 4095;
                    const long long ib = (long long)b * (EMB * SEQ) + l;
                    __half hh0 = __float2half(x0), hh1 = __float2half(x1);
                    __half ll0 = __float2half(x0 - __half2float(hh0));
                    __half ll1 = __float2half(x1 - __half2float(hh1));
                    Coh[ib + (long long)col * SEQ] = hh0;
                    Col[ib + (long long)col * SEQ] = ll0;
                    Coh[ib + (long long)(col + 1) * SEQ] = hh1;
                    Col[ib + (long long)(col + 1) * SEQ] = ll1;
                }
            }
        }
    }
}

// ---------------------------------------------------------------------------
// mask + scale + softmax; writes attn weights as (hi, lo) fp16
// ---------------------------------------------------------------------------
__global__ void softmax_mask_kernel(const float* __restrict__ E, const int* __restrict__ mask,
                                    __half* __restrict__ Ph, __half* __restrict__ Pl)
{
    const long long row = blockIdx.x;
    const float* e = E + row * (long long)SEQ;
    const int* mr = mask + row * (long long)SEQ;
    __half* ph = Ph + row * (long long)SEQ;
    __half* pl = Pl + row * (long long)SEQ;
    const int tid = threadIdx.x;
    const float scale = 0.044194173824159216f;   // 1/sqrt(512)

    float v[16];
    float lmax = -3.0e38f;
#pragma unroll
    for (int i = 0; i < 16; ++i) {
        const int idx = tid + (i << 8);
        float x = e[idx];
        x = (mr[idx] == 0) ? -1.0e20f : x;
        x *= scale;
        v[i] = x;
        lmax = fmaxf(lmax, x);
    }

    __shared__ float red[8];
#pragma unroll
    for (int o = 16; o > 0; o >>= 1)
        lmax = fmaxf(lmax, __shfl_xor_sync(0xffffffffu, lmax, o));
    if ((tid & 31) == 0) red[tid >> 5] = lmax;
    __syncthreads();
    float rowmax = red[0];
#pragma unroll
    for (int wv = 1; wv < 8; ++wv) rowmax = fmaxf(rowmax, red[wv]);
    __syncthreads();

    float lsum = 0.f;
#pragma unroll
    for (int i = 0; i < 16; ++i) {
        v[i] = __expf(v[i] - rowmax);
        lsum += v[i];
    }
#pragma unroll
    for (int o = 16; o > 0; o >>= 1)
        lsum += __shfl_xor_sync(0xffffffffu, lsum, o);
    if ((tid & 31) == 0) red[tid >> 5] = lsum;
    __syncthreads();
    float rowsum = 0.f;
#pragma unroll
    for (int wv = 0; wv < 8; ++wv) rowsum += red[wv];
    const float inv = 1.0f / rowsum;
#pragma unroll
    for (int i = 0; i < 16; ++i) {
        const int idx = tid + (i << 8);
        const float p = v[i] * inv;
        const __half h = __float2half(p);
        ph[idx] = h;
        pl[idx] = __float2half(p - __half2float(h));
    }
}

// ---------------------------------------------------------------------------
// Launch
// ---------------------------------------------------------------------------
extern "C" void kernel_launch(void* const* d_in, const int* in_sizes, int n_in,
                              void* d_out, int out_size)
{
    (void)in_sizes; (void)n_in; (void)out_size;

    const float* values = (const float*)d_in[0];
    const float* keys   = (const float*)d_in[1];
    const float* query  = (const float*)d_in[2];
    const int*   mask   = (const int*)  d_in[3];
    const float* Wv     = (const float*)d_in[4];
    const float* Wk     = (const float*)d_in[5];
    const float* Wq     = (const float*)d_in[6];
    const float* Wo     = (const float*)d_in[7];
    const float* bo     = (const float*)d_in[8];
    float* out = (float*)d_out;

    __half *vh, *vl, *kh, *kl, *qh, *ql;
    __half *Wvh, *Wvl, *Wkh, *Wkl, *Wqh, *Wql, *Woh, *Wol;
    __half *Qph, *Qpl, *Kph, *Kpl, *VTh, *VTl, *Ph, *Pl, *AOh, *AOl;
    float* E;
    cudaGetSymbolAddress((void**)&vh, g_vh);   cudaGetSymbolAddress((void**)&vl, g_vl);
    cudaGetSymbolAddress((void**)&kh, g_kh);   cudaGetSymbolAddress((void**)&kl, g_kl);
    cudaGetSymbolAddress((void**)&qh, g_qh);   cudaGetSymbolAddress((void**)&ql, g_ql);
    cudaGetSymbolAddress((void**)&Wvh, g_Wvh); cudaGetSymbolAddress((void**)&Wvl, g_Wvl);
    cudaGetSymbolAddress((void**)&Wkh, g_Wkh); cudaGetSymbolAddress((void**)&Wkl, g_Wkl);
    cudaGetSymbolAddress((void**)&Wqh, g_Wqh); cudaGetSymbolAddress((void**)&Wql, g_Wql);
    cudaGetSymbolAddress((void**)&Woh, g_Woh); cudaGetSymbolAddress((void**)&Wol, g_Wol);
    cudaGetSymbolAddress((void**)&Qph, g_Qph); cudaGetSymbolAddress((void**)&Qpl, g_Qpl);
    cudaGetSymbolAddress((void**)&Kph, g_Kph); cudaGetSymbolAddress((void**)&Kpl, g_Kpl);
    cudaGetSymbolAddress((void**)&VTh, g_VTh); cudaGetSymbolAddress((void**)&VTl, g_VTl);
    cudaGetSymbolAddress((void**)&Ph, g_Ph);   cudaGetSymbolAddress((void**)&Pl, g_Pl);
    cudaGetSymbolAddress((void**)&AOh, g_AOh); cudaGetSymbolAddress((void**)&AOl, g_AOl);
    cudaGetSymbolAddress((void**)&E, g_E);

    constexpr int SMEM = STAGES * STAGE_BYTES;   // 192 KB
    cudaFuncSetAttribute((const void*)mma_gemm<0>, cudaFuncAttributeMaxDynamicSharedMemorySize, SMEM);
    cudaFuncSetAttribute((const void*)mma_gemm<1>, cudaFuncAttributeMaxDynamicSharedMemorySize, SMEM);
    cudaFuncSetAttribute((const void*)mma_gemm<2>, cudaFuncAttributeMaxDynamicSharedMemorySize, SMEM);
    cudaFuncSetAttribute((const void*)mma_gemm<3>, cudaFuncAttributeMaxDynamicSharedMemorySize, SMEM);

    // 1) split inputs + weights into fp16 hi/lo
    const int n4_big = NTOK * EMB / 4;
    const int n4_w   = EMB * EMB / 4;
    cvt_hilo<<<(n4_big + 255) / 256, 256>>>((const float4*)values, (uint2*)vh, (uint2*)vl, n4_big);
    cvt_hilo<<<(n4_big + 255) / 256, 256>>>((const float4*)keys,   (uint2*)kh, (uint2*)kl, n4_big);
    cvt_hilo<<<(n4_big + 255) / 256, 256>>>((const float4*)query,  (uint2*)qh, (uint2*)ql, n4_big);
    cvt_hilo<<<(n4_w + 255) / 256, 256>>>((const float4*)Wv, (uint2*)Wvh, (uint2*)Wvl, n4_w);
    cvt_hilo<<<(n4_w + 255) / 256, 256>>>((const float4*)Wk, (uint2*)Wkh, (uint2*)Wkl, n4_w);
    cvt_hilo<<<(n4_w + 255) / 256, 256>>>((const float4*)Wq, (uint2*)Wqh, (uint2*)Wql, n4_w);
    cvt_hilo<<<(n4_w + 255) / 256, 256>>>((const float4*)Wo, (uint2*)Woh, (uint2*)Wol, n4_w);

    const dim3 blk(256);
    const long long sQK = (long long)SEQ * EMB;
    const long long sE  = (long long)SEQ * SEQ;

    // 2) projections: [16384,512] = X @ W^T
    const dim3 gproj(EMB / 128, NTOK / 128, 1);
    mma_gemm<1><<<gproj, blk, SMEM>>>(qh, ql, Wqh, Wql, nullptr, Qph, Qpl, nullptr,
                                      EMB, EMB, 0, 0, 0);
    mma_gemm<1><<<gproj, blk, SMEM>>>(kh, kl, Wkh, Wkl, nullptr, Kph, Kpl, nullptr,
                                      EMB, EMB, 0, 0, 0);
    mma_gemm<2><<<gproj, blk, SMEM>>>(vh, vl, Wvh, Wvl, nullptr, VTh, VTl, nullptr,
                                      EMB, EMB, 0, 0, 0);

    // 3) energy: per-batch [4096,4096] = Qp @ Kp^T (fp32 out)
    const dim3 ge(SEQ / 128, SEQ / 128, NB);
    mma_gemm<0><<<ge, blk, SMEM>>>(Qph, Qpl, Kph, Kpl, E, nullptr, nullptr, nullptr,
                                   EMB, SEQ, sQK, sQK, sE);

    // 4) mask + scale + softmax -> attn hi/lo fp16
    softmax_mask_kernel<<<NB * SEQ, 256>>>(E, mask, Ph, Pl);

    // 5) attn @ V: per-batch [4096,512] = P @ VT^T (hi/lo out)
    const dim3 gav(EMB / 128, SEQ / 128, NB);
    mma_gemm<1><<<gav, blk, SMEM>>>(Ph, Pl, VTh, VTl, nullptr, AOh, AOl, nullptr,
                                    SEQ, EMB, sE, sQK, sQK);

    // 6) output projection + bias (fp32 out)
    mma_gemm<3><<<gproj, blk, SMEM>>>(AOh, AOl, Woh, Wol, out, nullptr, nullptr, bo,
                                      EMB, EMB, 0, 0, 0);
}

// round 4
// speedup vs baseline: 2.8773x; 1.0250x over previous
#include <cuda_runtime.h>
#include <cuda_fp16.h>
#include <cstdint>

#define NB   4
#define SEQ  4096
#define EMB  512
#define NTOK (NB * SEQ)   // 16384

// ---------------------------------------------------------------------------
// Device scratch
// ---------------------------------------------------------------------------
__device__ __half g_vh[(size_t)NTOK * EMB], g_vl[(size_t)NTOK * EMB];
__device__ __half g_kh[(size_t)NTOK * EMB], g_kl[(size_t)NTOK * EMB];
__device__ __half g_qh[(size_t)NTOK * EMB], g_ql[(size_t)NTOK * EMB];
__device__ __half g_Wvh[EMB * EMB], g_Wvl[EMB * EMB];
__device__ __half g_Wkh[EMB * EMB], g_Wkl[EMB * EMB];
__device__ __half g_Wqh[EMB * EMB], g_Wql[EMB * EMB];
__device__ __half g_Woh[EMB * EMB], g_Wol[EMB * EMB];
__device__ __half g_Qph[(size_t)NTOK * EMB], g_Qpl[(size_t)NTOK * EMB];
__device__ __half g_Kph[(size_t)NTOK * EMB], g_Kpl[(size_t)NTOK * EMB];
__device__ __half g_VTh[(size_t)NTOK * EMB], g_VTl[(size_t)NTOK * EMB]; // [b][d][l]
__device__ float  g_E  [(size_t)NB * SEQ * SEQ];
__device__ __half g_Ph [(size_t)NB * SEQ * SEQ], g_Pl[(size_t)NB * SEQ * SEQ];
__device__ __half g_AOh[(size_t)NTOK * EMB], g_AOl[(size_t)NTOK * EMB];

// ---------------------------------------------------------------------------
// helpers
// ---------------------------------------------------------------------------
__device__ __forceinline__ uint32_t smem_u32_of(const void* p) {
    uint32_t a;
    asm("{ .reg .u64 t; cvta.to.shared.u64 t, %1; cvt.u32.u64 %0, t; }" : "=r"(a) : "l"(p));
    return a;
}

__device__ __forceinline__ void ldsm4(uint32_t* r, uint32_t addr) {
    asm volatile("ldmatrix.sync.aligned.m8n8.x4.shared.b16 {%0,%1,%2,%3}, [%4];"
                 : "=r"(r[0]), "=r"(r[1]), "=r"(r[2]), "=r"(r[3]) : "r"(addr));
}

__device__ __forceinline__ void mma16816(float* c, const uint32_t* a, const uint32_t* b) {
    asm volatile(
        "mma.sync.aligned.m16n8k16.row.col.f32.f16.f16.f32 "
        "{%0,%1,%2,%3}, {%4,%5,%6,%7}, {%8,%9}, {%0,%1,%2,%3};"
        : "+f"(c[0]), "+f"(c[1]), "+f"(c[2]), "+f"(c[3])
        : "r"(a[0]), "r"(a[1]), "r"(a[2]), "r"(a[3]), "r"(b[0]), "r"(b[1]));
}

#define CP_ASYNC16(dst, src) \
    asm volatile("cp.async.cg.shared.global [%0], [%1], 16;" :: "r"(dst), "l"(src))
#define CP_COMMIT() asm volatile("cp.async.commit_group;")
#define CP_WAIT(n)  asm volatile("cp.async.wait_group %0;" :: "n"(n))

__device__ __forceinline__ uint32_t packh2(__half a, __half b) {
    __half2 h = __halves2half2(a, b);
    return *(uint32_t*)&h;
}

// packed 2-logical-rows-per-128B layout + SW128 swizzle (tile = 128 rows x 32 halves)
__device__ __forceinline__ uint32_t ldoff(int row, int u) {
    uint32_t off = (uint32_t)(((row >> 1) << 7) | ((row & 1) << 6) | (u << 4));
    return off ^ ((off >> 3) & 0x70);
}

#define STAGES 3
#define TILE_B  8192u       // 128 rows * 64B
#define STAGE_B 32768u      // 4 tiles
#define SMEM_SZ (STAGES * STAGE_B)   // 96 KB

// ---------------------------------------------------------------------------
// GEMM core: acc[4][4][4] += 3-term fp16 split of A[128,K] @ B[128,K]^T tile
// ---------------------------------------------------------------------------
__device__ __forceinline__ void gemm_core(
    const __half* __restrict__ gAh, const __half* __restrict__ gAl,
    const __half* __restrict__ gBh, const __half* __restrict__ gBl,
    int K, uint32_t smem_base, float acc[4][4][4])
{
    const int tid = threadIdx.x;
    const int lane = tid & 31;
    const int w = tid >> 5;
    const int wm = w >> 2, wn = w & 3;

    const int ld_row = tid >> 2;     // 0..63 (+64 second iter)
    const int ld_u   = tid & 3;

    const int a_row0 = wm * 64 + (lane & 15);
    const int a_uadd = lane >> 4;
    const int b_row0 = wn * 32 + (lane & 7) + ((lane >> 4) << 3);
    const int b_uadd = (lane >> 3) & 1;

    auto load_chunk = [&](int c) {
        const uint32_t sb = smem_base + (uint32_t)(c % STAGES) * STAGE_B;
        const long long koff = (long long)c * 32;
        const __half* gp[4] = { gAh + koff, gAl + koff, gBh + koff, gBl + koff };
#pragma unroll
        for (int t = 0; t < 4; ++t) {
#pragma unroll
            for (int i = 0; i < 2; ++i) {
                const int row = ld_row + i * 64;
                const void* g = gp[t] + (long long)row * K + ld_u * 8;
                CP_ASYNC16(sb + t * TILE_B + ldoff(row, ld_u), g);
            }
        }
        CP_COMMIT();
    };

    const int nCh = K >> 5;
#pragma unroll 1
    for (int c = 0; c < STAGES; ++c) load_chunk(c);

#pragma unroll 1
    for (int c = 0; c < nCh; ++c) {
        CP_WAIT(STAGES - 1);
        __syncthreads();
        const uint32_t sb = smem_base + (uint32_t)(c % STAGES) * STAGE_B;

#pragma unroll
        for (int ks = 0; ks < 2; ++ks) {
            uint32_t bH[4][2], bL[4][2];
#pragma unroll
            for (int nh = 0; nh < 2; ++nh) {
                const uint32_t off = ldoff(b_row0 + nh * 16, ks * 2 + b_uadd);
                uint32_t r4[4];
                ldsm4(r4, sb + 2 * TILE_B + off);
                bH[2 * nh][0] = r4[0]; bH[2 * nh][1] = r4[1];
                bH[2 * nh + 1][0] = r4[2]; bH[2 * nh + 1][1] = r4[3];
                ldsm4(r4, sb + 3 * TILE_B + off);
                bL[2 * nh][0] = r4[0]; bL[2 * nh][1] = r4[1];
                bL[2 * nh + 1][0] = r4[2]; bL[2 * nh + 1][1] = r4[3];
            }
#pragma unroll
            for (int mf = 0; mf < 4; ++mf) {
                const uint32_t off = ldoff(a_row0 + mf * 16, ks * 2 + a_uadd);
                uint32_t aH[4], aL[4];
                ldsm4(aH, sb + off);
                ldsm4(aL, sb + TILE_B + off);
#pragma unroll
                for (int nf = 0; nf < 4; ++nf) {
                    mma16816(acc[mf][nf], aH, bH[nf]);
                    mma16816(acc[mf][nf], aH, bL[nf]);
                    mma16816(acc[mf][nf], aL, bH[nf]);
                }
            }
        }

        __syncthreads();
        if (c + STAGES < nCh) load_chunk(c + STAGES);
        else CP_COMMIT();   // keep group accounting aligned
    }
}

// ---------------------------------------------------------------------------
// Generic GEMM kernel.  EPI: 0 = fp32 C; 1 = hi/lo fp16 row-major; 3 = fp32+bias
// ---------------------------------------------------------------------------
template <int EPI>
__global__ void __launch_bounds__(256, 2)
mma_gemm(const __half* __restrict__ Ah, const __half* __restrict__ Al,
         const __half* __restrict__ Bh, const __half* __restrict__ Bl,
         float* __restrict__ Cf, __half* __restrict__ Coh,
         __half* __restrict__ Col, const float* __restrict__ bias,
         int K, int ldC, long long sA, long long sB, long long sC)
{
    extern __shared__ __align__(1024) char smem[];
    const uint32_t smem_base = smem_u32_of(smem);

    const int tid = threadIdx.x;
    const int lane = tid & 31;
    const int w = tid >> 5;
    const int wm = w >> 2, wn = w & 3;
    const int z = blockIdx.z;
    const int bm = blockIdx.y * 128;
    const int bn = blockIdx.x * 128;

    float acc[4][4][4] = {};
    gemm_core(Ah + (long long)z * sA + (long long)bm * K,
              Al + (long long)z * sA + (long long)bm * K,
              Bh + (long long)z * sB + (long long)bn * K,
              Bl + (long long)z * sB + (long long)bn * K,
              K, smem_base, acc);

    const int g = lane >> 2, tig = lane & 3;
#pragma unroll
    for (int mf = 0; mf < 4; ++mf) {
#pragma unroll
        for (int h2 = 0; h2 < 2; ++h2) {
            const int row = bm + wm * 64 + mf * 16 + g + h2 * 8;
#pragma unroll
            for (int nf = 0; nf < 4; ++nf) {
                const int col = bn + wn * 32 + nf * 8 + 2 * tig;
                const float x0 = acc[mf][nf][h2 * 2 + 0];
                const float x1 = acc[mf][nf][h2 * 2 + 1];
                if (EPI == 0) {
                    *(float2*)(Cf + (long long)z * sC + (long long)row * ldC + col) =
                        make_float2(x0, x1);
                } else if (EPI == 3) {
                    *(float2*)(Cf + (long long)z * sC + (long long)row * ldC + col) =
                        make_float2(x0 + bias[col], x1 + bias[col + 1]);
                } else {
                    const long long base = (long long)z * sC + (long long)row * ldC + col;
                    __half hh0 = __float2half(x0), hh1 = __float2half(x1);
                    __half ll0 = __float2half(x0 - __half2float(hh0));
                    __half ll1 = __float2half(x1 - __half2float(hh1));
                    *(uint32_t*)(Coh + base) = packh2(hh0, hh1);
                    *(uint32_t*)(Col + base) = packh2(ll0, ll1);
                }
            }
        }
    }
}

// ---------------------------------------------------------------------------
// Merged Q/K/V projection kernel; z selects projection; V writes transposed
// ---------------------------------------------------------------------------
struct Ptrs3 {
    const __half *Ah, *Al, *Bh, *Bl;
    __half *Oh, *Ol;
};
struct QKVArgs { Ptrs3 p[3]; };

__global__ void __launch_bounds__(256, 2)
qkv_gemm(QKVArgs args)
{
    extern __shared__ __align__(1024) char smem[];
    const uint32_t smem_base = smem_u32_of(smem);

    const int tid = threadIdx.x;
    const int lane = tid & 31;
    const int w = tid >> 5;
    const int wm = w >> 2, wn = w & 3;
    const int z = blockIdx.z;
    const int bm = blockIdx.y * 128;
    const int bn = blockIdx.x * 128;
    const Ptrs3 pp = args.p[z];

    float acc[4][4][4] = {};
    gemm_core(pp.Ah + (long long)bm * EMB, pp.Al + (long long)bm * EMB,
              pp.Bh + (long long)bn * EMB, pp.Bl + (long long)bn * EMB,
              EMB, smem_base, acc);

    const int g = lane >> 2, tig = lane & 3;
    const bool doT = (z == 2);
#pragma unroll
    for (int mf = 0; mf < 4; ++mf) {
#pragma unroll
        for (int h2 = 0; h2 < 2; ++h2) {
            const int row = bm + wm * 64 + mf * 16 + g + h2 * 8;
#pragma unroll
            for (int nf = 0; nf < 4; ++nf) {
                const int col = bn + wn * 32 + nf * 8 + 2 * tig;
                const float x0 = acc[mf][nf][h2 * 2 + 0];
                const float x1 = acc[mf][nf][h2 * 2 + 1];
                __half hh0 = __float2half(x0), hh1 = __float2half(x1);
                __half ll0 = __float2half(x0 - __half2float(hh0));
                __half ll1 = __float2half(x1 - __half2float(hh1));
                if (!doT) {
                    const long long base = (long long)row * EMB + col;
                    *(uint32_t*)(pp.Oh + base) = packh2(hh0, hh1);
                    *(uint32_t*)(pp.Ol + base) = packh2(ll0, ll1);
                } else {  // transposed: dest [b][d=col][l=row&4095]
                    const int b = row >> 12, l = row & 4095;
                    const long long ib = (long long)b * (EMB * SEQ) + l;
                    pp.Oh[ib + (long long)col * SEQ] = hh0;
                    pp.Ol[ib + (long long)col * SEQ] = ll0;
                    pp.Oh[ib + (long long)(col + 1) * SEQ] = hh1;
                    pp.Ol[ib + (long long)(col + 1) * SEQ] = ll1;
                }
            }
        }
    }
}

// ---------------------------------------------------------------------------
// Merged fp32 -> (hi, lo) fp16 split conversion over all 7 tensors
// ---------------------------------------------------------------------------
struct CvtArgs {
    const float4* x[7];
    uint2* h[7];
    uint2* l[7];
};
#define BIG4  (NTOK * EMB / 4)   // 2097152
#define W4    (EMB * EMB / 4)    // 65536
#define CVT_TOT (3 * BIG4 + 4 * W4)

__global__ void cvt_all(CvtArgs args)
{
    int idx = blockIdx.x * 256 + threadIdx.x;
    if (idx >= CVT_TOT) return;
    int seg, off;
    if (idx < 3 * BIG4) { seg = idx / BIG4; off = idx - seg * BIG4; }
    else { int j = idx - 3 * BIG4; seg = 3 + j / W4; off = j & (W4 - 1); }
    float4 v = args.x[seg][off];
    __half h0 = __float2half(v.x), h1 = __float2half(v.y);
    __half h2 = __float2half(v.z), h3 = __float2half(v.w);
    __half l0 = __float2half(v.x - __half2float(h0));
    __half l1 = __float2half(v.y - __half2float(h1));
    __half l2 = __float2half(v.z - __half2float(h2));
    __half l3 = __float2half(v.w - __half2float(h3));
    args.h[seg][off] = make_uint2(packh2(h0, h1), packh2(h2, h3));
    args.l[seg][off] = make_uint2(packh2(l0, l1), packh2(l2, l3));
}

// ---------------------------------------------------------------------------
// mask + scale + softmax (vectorized); writes attn weights as (hi, lo) fp16
// ---------------------------------------------------------------------------
__global__ void softmax_mask_kernel(const float* __restrict__ E, const int* __restrict__ mask,
                                    __half* __restrict__ Ph, __half* __restrict__ Pl)
{
    const long long row = blockIdx.x;
    const float4* e4 = (const float4*)(E + row * (long long)SEQ);
    const int4* m4 = (const int4*)(mask + row * (long long)SEQ);
    uint2* ph2 = (uint2*)(Ph + row * (long long)SEQ);
    uint2* pl2 = (uint2*)(Pl + row * (long long)SEQ);
    const int tid = threadIdx.x;
    const float scale = 0.044194173824159216f;   // 1/sqrt(512)

    float v[16];
    float lmax = -3.0e38f;
#pragma unroll
    for (int i = 0; i < 4; ++i) {
        const int idx = tid + (i << 8);
        float4 x = e4[idx];
        int4 mm = m4[idx];
        v[4*i+0] = (mm.x == 0 ? -1.0e20f : x.x) * scale;
        v[4*i+1] = (mm.y == 0 ? -1.0e20f : x.y) * scale;
        v[4*i+2] = (mm.z == 0 ? -1.0e20f : x.z) * scale;
        v[4*i+3] = (mm.w == 0 ? -1.0e20f : x.w) * scale;
        lmax = fmaxf(fmaxf(fmaxf(v[4*i+0], v[4*i+1]), fmaxf(v[4*i+2], v[4*i+3])), lmax);
    }

    __shared__ float red[8];
#pragma unroll
    for (int o = 16; o > 0; o >>= 1)
        lmax = fmaxf(lmax, __shfl_xor_sync(0xffffffffu, lmax, o));
    if ((tid & 31) == 0) red[tid >> 5] = lmax;
    __syncthreads();
    float rowmax = red[0];
#pragma unroll
    for (int wv = 1; wv < 8; ++wv) rowmax = fmaxf(rowmax, red[wv]);
    __syncthreads();

    float lsum = 0.f;
#pragma unroll
    for (int i = 0; i < 16; ++i) {
        v[i] = __expf(v[i] - rowmax);
        lsum += v[i];
    }
#pragma unroll
    for (int o = 16; o > 0; o >>= 1)
        lsum += __shfl_xor_sync(0xffffffffu, lsum, o);
    if ((tid & 31) == 0) red[tid >> 5] = lsum;
    __syncthreads();
    float rowsum = 0.f;
#pragma unroll
    for (int wv = 0; wv < 8; ++wv) rowsum += red[wv];
    const float inv = 1.0f / rowsum;
#pragma unroll
    for (int i = 0; i < 4; ++i) {
        const int idx = tid + (i << 8);
        float p0 = v[4*i+0] * inv, p1 = v[4*i+1] * inv;
        float p2 = v[4*i+2] * inv, p3 = v[4*i+3] * inv;
        __half a0 = __float2half(p0), a1 = __float2half(p1);
        __half a2 = __float2half(p2), a3 = __float2half(p3);
        ph2[idx] = make_uint2(packh2(a0, a1), packh2(a2, a3));
        pl2[idx] = make_uint2(
            packh2(__float2half(p0 - __half2float(a0)), __float2half(p1 - __half2float(a1))),
            packh2(__float2half(p2 - __half2float(a2)), __float2half(p3 - __half2float(a3))));
    }
}

// ---------------------------------------------------------------------------
// Launch
// ---------------------------------------------------------------------------
extern "C" void kernel_launch(void* const* d_in, const int* in_sizes, int n_in,
                              void* d_out, int out_size)
{
    (void)in_sizes; (void)n_in; (void)out_size;

    const float* values = (const float*)d_in[0];
    const float* keys   = (const float*)d_in[1];
    const float* query  = (const float*)d_in[2];
    const int*   mask   = (const int*)  d_in[3];
    const float* Wv     = (const float*)d_in[4];
    const float* Wk     = (const float*)d_in[5];
    const float* Wq     = (const float*)d_in[6];
    const float* Wo     = (const float*)d_in[7];
    const float* bo     = (const float*)d_in[8];
    float* out = (float*)d_out;

    __half *vh, *vl, *kh, *kl, *qh, *ql;
    __half *Wvh, *Wvl, *Wkh, *Wkl, *Wqh, *Wql, *Woh, *Wol;
    __half *Qph, *Qpl, *Kph, *Kpl, *VTh, *VTl, *Ph, *Pl, *AOh, *AOl;
    float* E;
    cudaGetSymbolAddress((void**)&vh, g_vh);   cudaGetSymbolAddress((void**)&vl, g_vl);
    cudaGetSymbolAddress((void**)&kh, g_kh);   cudaGetSymbolAddress((void**)&kl, g_kl);
    cudaGetSymbolAddress((void**)&qh, g_qh);   cudaGetSymbolAddress((void**)&ql, g_ql);
    cudaGetSymbolAddress((void**)&Wvh, g_Wvh); cudaGetSymbolAddress((void**)&Wvl, g_Wvl);
    cudaGetSymbolAddress((void**)&Wkh, g_Wkh); cudaGetSymbolAddress((void**)&Wkl, g_Wkl);
    cudaGetSymbolAddress((void**)&Wqh, g_Wqh); cudaGetSymbolAddress((void**)&Wql, g_Wql);
    cudaGetSymbolAddress((void**)&Woh, g_Woh); cudaGetSymbolAddress((void**)&Wol, g_Wol);
    cudaGetSymbolAddress((void**)&Qph, g_Qph); cudaGetSymbolAddress((void**)&Qpl, g_Qpl);
    cudaGetSymbolAddress((void**)&Kph, g_Kph); cudaGetSymbolAddress((void**)&Kpl, g_Kpl);
    cudaGetSymbolAddress((void**)&VTh, g_VTh); cudaGetSymbolAddress((void**)&VTl, g_VTl);
    cudaGetSymbolAddress((void**)&Ph, g_Ph);   cudaGetSymbolAddress((void**)&Pl, g_Pl);
    cudaGetSymbolAddress((void**)&AOh, g_AOh); cudaGetSymbolAddress((void**)&AOl, g_AOl);
    cudaGetSymbolAddress((void**)&E, g_E);

    cudaFuncSetAttribute((const void*)mma_gemm<0>, cudaFuncAttributeMaxDynamicSharedMemorySize, SMEM_SZ);
    cudaFuncSetAttribute((const void*)mma_gemm<1>, cudaFuncAttributeMaxDynamicSharedMemorySize, SMEM_SZ);
    cudaFuncSetAttribute((const void*)mma_gemm<3>, cudaFuncAttributeMaxDynamicSharedMemorySize, SMEM_SZ);
    cudaFuncSetAttribute((const void*)qkv_gemm, cudaFuncAttributeMaxDynamicSharedMemorySize, SMEM_SZ);

    // 1) split inputs + weights into fp16 hi/lo (single launch)
    CvtArgs ca;
    ca.x[0] = (const float4*)query;  ca.h[0] = (uint2*)qh;  ca.l[0] = (uint2*)ql;
    ca.x[1] = (const float4*)keys;   ca.h[1] = (uint2*)kh;  ca.l[1] = (uint2*)kl;
    ca.x[2] = (const float4*)values; ca.h[2] = (uint2*)vh;  ca.l[2] = (uint2*)vl;
    ca.x[3] = (const float4*)Wq;     ca.h[3] = (uint2*)Wqh; ca.l[3] = (uint2*)Wql;
    ca.x[4] = (const float4*)Wk;     ca.h[4] = (uint2*)Wkh; ca.l[4] = (uint2*)Wkl;
    ca.x[5] = (const float4*)Wv;     ca.h[5] = (uint2*)Wvh; ca.l[5] = (uint2*)Wvl;
    ca.x[6] = (const float4*)Wo;     ca.h[6] = (uint2*)Woh; ca.l[6] = (uint2*)Wol;
    cvt_all<<<(CVT_TOT + 255) / 256, 256>>>(ca);

    const dim3 blk(256);
    const long long sQK = (long long)SEQ * EMB;
    const long long sE  = (long long)SEQ * SEQ;

    // 2) merged projections: z=0 Q, z=1 K, z=2 V(transposed)
    QKVArgs qa;
    qa.p[0] = { qh, ql, Wqh, Wql, Qph, Qpl };
    qa.p[1] = { kh, kl, Wkh, Wkl, Kph, Kpl };
    qa.p[2] = { vh, vl, Wvh, Wvl, VTh, VTl };
    qkv_gemm<<<dim3(EMB / 128, NTOK / 128, 3), blk, SMEM_SZ>>>(qa);

    // 3) energy: per-batch [4096,4096] = Qp @ Kp^T (fp32 out)
    mma_gemm<0><<<dim3(SEQ / 128, SEQ / 128, NB), blk, SMEM_SZ>>>(
        Qph, Qpl, Kph, Kpl, E, nullptr, nullptr, nullptr, EMB, SEQ, sQK, sQK, sE);

    // 4) mask + scale + softmax -> attn hi/lo fp16
    softmax_mask_kernel<<<NB * SEQ, 256>>>(E, mask, Ph, Pl);

    // 5) attn @ V: per-batch [4096,512] = P @ VT^T (hi/lo out)
    mma_gemm<1><<<dim3(EMB / 128, SEQ / 128, NB), blk, SMEM_SZ>>>(
        Ph, Pl, VTh, VTl, nullptr, AOh, AOl, nullptr, SEQ, EMB, sE, sQK, sQK);

    // 6) output projection + bias (fp32 out)
    mma_gemm<3><<<dim3(EMB / 128, NTOK / 128, 1), blk, SMEM_SZ>>>(
        AOh, AOl, Woh, Wol, out, nullptr, nullptr, bo, EMB, EMB, 0, 0, 0);
}

// round 5
// speedup vs baseline: 4.1770x; 1.4517x over previous
#include <cuda_runtime.h>
#include <cuda_fp16.h>
#include <cstdint>

#define NB   4
#define SEQ  4096
#define EMB  512
#define NTOK (NB * SEQ)   // 16384

// ---------------------------------------------------------------------------
// Device scratch
// ---------------------------------------------------------------------------
__device__ __half g_vh[(size_t)NTOK * EMB], g_vl[(size_t)NTOK * EMB];
__device__ __half g_kh[(size_t)NTOK * EMB], g_kl[(size_t)NTOK * EMB];
__device__ __half g_qh[(size_t)NTOK * EMB], g_ql[(size_t)NTOK * EMB];
__device__ __half g_Wvh[EMB * EMB], g_Wvl[EMB * EMB];
__device__ __half g_Wkh[EMB * EMB], g_Wkl[EMB * EMB];
__device__ __half g_Wqh[EMB * EMB], g_Wql[EMB * EMB];
__device__ __half g_Woh[EMB * EMB], g_Wol[EMB * EMB];
__device__ __half g_Qph[(size_t)NTOK * EMB];                        // hi only
__device__ __half g_Kph[(size_t)NTOK * EMB];                        // hi only
__device__ __half g_VTh[(size_t)NTOK * EMB], g_VTl[(size_t)NTOK * EMB]; // [b][d][l]
__device__ float  g_E  [(size_t)NB * SEQ * SEQ];
__device__ __half g_Ph [(size_t)NB * SEQ * SEQ];                    // hi only
__device__ __half g_AOh[(size_t)NTOK * EMB], g_AOl[(size_t)NTOK * EMB];

// ---------------------------------------------------------------------------
// helpers
// ---------------------------------------------------------------------------
__device__ __forceinline__ uint32_t smem_u32_of(const void* p) {
    uint32_t a;
    asm("{ .reg .u64 t; cvta.to.shared.u64 t, %1; cvt.u32.u64 %0, t; }" : "=r"(a) : "l"(p));
    return a;
}

__device__ __forceinline__ void ldsm4(uint32_t* r, uint32_t addr) {
    asm volatile("ldmatrix.sync.aligned.m8n8.x4.shared.b16 {%0,%1,%2,%3}, [%4];"
                 : "=r"(r[0]), "=r"(r[1]), "=r"(r[2]), "=r"(r[3]) : "r"(addr));
}

__device__ __forceinline__ void mma16816(float* c, const uint32_t* a, const uint32_t* b) {
    asm volatile(
        "mma.sync.aligned.m16n8k16.row.col.f32.f16.f16.f32 "
        "{%0,%1,%2,%3}, {%4,%5,%6,%7}, {%8,%9}, {%0,%1,%2,%3};"
        : "+f"(c[0]), "+f"(c[1]), "+f"(c[2]), "+f"(c[3])
        : "r"(a[0]), "r"(a[1]), "r"(a[2]), "r"(a[3]), "r"(b[0]), "r"(b[1]));
}

#define CP_ASYNC16(dst, src) \
    asm volatile("cp.async.cg.shared.global [%0], [%1], 16;" :: "r"(dst), "l"(src))
#define CP_COMMIT() asm volatile("cp.async.commit_group;")
#define CP_WAIT(n)  asm volatile("cp.async.wait_group %0;" :: "n"(n))

__device__ __forceinline__ uint32_t packh2(__half a, __half b) {
    __half2 h = __halves2half2(a, b);
    return *(uint32_t*)&h;
}

// packed 2-logical-rows-per-128B layout + SW128 swizzle (tile = 128 rows x 32 halves)
__device__ __forceinline__ uint32_t ldoff(int row, int u) {
    uint32_t off = (uint32_t)(((row >> 1) << 7) | ((row & 1) << 6) | (u << 4));
    return off ^ ((off >> 3) & 0x70);
}

#define STAGES 3
#define TILE_B  8192u       // 128 rows * 64B

// ---------------------------------------------------------------------------
// GEMM core templated on TERMS:
//   TERMS=1: AhBh                      tiles {Ah, Bh}
//   TERMS=2: AhBh + AhBl               tiles {Ah, Bh, Bl}
//   TERMS=3: AhBh + AhBl + AlBh        tiles {Ah, Al, Bh, Bl}
// A,B are K-contiguous [128, K] tiles; acc[4][4][4] per thread.
// ---------------------------------------------------------------------------
template <int TERMS>
__device__ __forceinline__ void gemm_core(
    const __half* __restrict__ gAh, const __half* __restrict__ gAl,
    const __half* __restrict__ gBh, const __half* __restrict__ gBl,
    int K, uint32_t smem_base, float acc[4][4][4])
{
    constexpr int A2 = (TERMS == 3) ? 1 : 0;
    constexpr int B2 = (TERMS >= 2) ? 1 : 0;
    constexpr int NT = 2 + A2 + B2;
    constexpr uint32_t STAGE_B = NT * TILE_B;
    constexpr uint32_t T_AH = 0;
    constexpr uint32_t T_AL = TILE_B;                 // valid iff A2
    constexpr uint32_t T_BH = (1 + A2) * TILE_B;
    constexpr uint32_t T_BL = (2 + A2) * TILE_B;      // valid iff B2

    const int tid = threadIdx.x;
    const int lane = tid & 31;
    const int w = tid >> 5;
    const int wm = w >> 2, wn = w & 3;

    const int ld_row = tid >> 2;     // 0..63 (+64 second iter)
    const int ld_u   = tid & 3;

    const int a_row0 = wm * 64 + (lane & 15);
    const int a_uadd = lane >> 4;
    const int b_row0 = wn * 32 + (lane & 7) + ((lane >> 4) << 3);
    const int b_uadd = (lane >> 3) & 1;

    auto load_chunk = [&](int c) {
        const uint32_t sb = smem_base + (uint32_t)(c % STAGES) * STAGE_B;
        const long long koff = (long long)c * 32;
        const __half* gp[NT];
        gp[0] = gAh + koff;
        if (A2) gp[1] = gAl + koff;
        gp[1 + A2] = gBh + koff;
        if (B2) gp[2 + A2] = gBl + koff;
#pragma unroll
        for (int t = 0; t < NT; ++t) {
#pragma unroll
            for (int i = 0; i < 2; ++i) {
                const int row = ld_row + i * 64;
                const void* g = gp[t] + (long long)row * K + ld_u * 8;
                CP_ASYNC16(sb + t * TILE_B + ldoff(row, ld_u), g);
            }
        }
        CP_COMMIT();
    };

    const int nCh = K >> 5;
#pragma unroll 1
    for (int c = 0; c < STAGES; ++c) load_chunk(c);

#pragma unroll 1
    for (int c = 0; c < nCh; ++c) {
        CP_WAIT(STAGES - 1);
        __syncthreads();
        const uint32_t sb = smem_base + (uint32_t)(c % STAGES) * STAGE_B;

#pragma unroll
        for (int ks = 0; ks < 2; ++ks) {
            uint32_t bH[4][2], bL[4][2];
#pragma unroll
            for (int nh = 0; nh < 2; ++nh) {
                const uint32_t off = ldoff(b_row0 + nh * 16, ks * 2 + b_uadd);
                uint32_t r4[4];
                ldsm4(r4, sb + T_BH + off);
                bH[2 * nh][0] = r4[0]; bH[2 * nh][1] = r4[1];
                bH[2 * nh + 1][0] = r4[2]; bH[2 * nh + 1][1] = r4[3];
                if (B2) {
                    ldsm4(r4, sb + T_BL + off);
                    bL[2 * nh][0] = r4[0]; bL[2 * nh][1] = r4[1];
                    bL[2 * nh + 1][0] = r4[2]; bL[2 * nh + 1][1] = r4[3];
                }
            }
#pragma unroll
            for (int mf = 0; mf < 4; ++mf) {
                const uint32_t off = ldoff(a_row0 + mf * 16, ks * 2 + a_uadd);
                uint32_t aH[4], aL[4];
                ldsm4(aH, sb + T_AH + off);
                if (A2) ldsm4(aL, sb + T_AL + off);
#pragma unroll
                for (int nf = 0; nf < 4; ++nf) {
                    mma16816(acc[mf][nf], aH, bH[nf]);
                    if (B2) mma16816(acc[mf][nf], aH, bL[nf]);
                    if (A2) mma16816(acc[mf][nf], aL, bH[nf]);
                }
            }
        }

        __syncthreads();
        if (c + STAGES < nCh) load_chunk(c + STAGES);
        else CP_COMMIT();   // keep group accounting aligned
    }
}

// ---------------------------------------------------------------------------
// Generic GEMM kernel.
// EPI: 0 = fp32 C; 1 = hi/lo fp16 row-major; 3 = fp32 + bias
// ---------------------------------------------------------------------------
template <int TERMS, int EPI>
__global__ void __launch_bounds__(256, 2)
mma_gemm(const __half* __restrict__ Ah, const __half* __restrict__ Al,
         const __half* __restrict__ Bh, const __half* __restrict__ Bl,
         float* __restrict__ Cf, __half* __restrict__ Coh,
         __half* __restrict__ Col, const float* __restrict__ bias,
         int K, int ldC, long long sA, long long sB, long long sC)
{
    extern __shared__ __align__(1024) char smem[];
    const uint32_t smem_base = smem_u32_of(smem);

    const int tid = threadIdx.x;
    const int lane = tid & 31;
    const int w = tid >> 5;
    const int wm = w >> 2, wn = w & 3;
    const int z = blockIdx.z;
    const int bm = blockIdx.y * 128;
    const int bn = blockIdx.x * 128;

    float acc[4][4][4] = {};
    gemm_core<TERMS>(Ah + (long long)z * sA + (long long)bm * K,
                     (TERMS == 3) ? Al + (long long)z * sA + (long long)bm * K : nullptr,
                     Bh + (long long)z * sB + (long long)bn * K,
                     (TERMS >= 2) ? Bl + (long long)z * sB + (long long)bn * K : nullptr,
                     K, smem_base, acc);

    const int g = lane >> 2, tig = lane & 3;
#pragma unroll
    for (int mf = 0; mf < 4; ++mf) {
#pragma unroll
        for (int h2 = 0; h2 < 2; ++h2) {
            const int row = bm + wm * 64 + mf * 16 + g + h2 * 8;
#pragma unroll
            for (int nf = 0; nf < 4; ++nf) {
                const int col = bn + wn * 32 + nf * 8 + 2 * tig;
                const float x0 = acc[mf][nf][h2 * 2 + 0];
                const float x1 = acc[mf][nf][h2 * 2 + 1];
                if (EPI == 0) {
                    *(float2*)(Cf + (long long)z * sC + (long long)row * ldC + col) =
                        make_float2(x0, x1);
                } else if (EPI == 3) {
                    *(float2*)(Cf + (long long)z * sC + (long long)row * ldC + col) =
                        make_float2(x0 + bias[col], x1 + bias[col + 1]);
                } else {
                    const long long base = (long long)z * sC + (long long)row * ldC + col;
                    __half hh0 = __float2half(x0), hh1 = __float2half(x1);
                    __half ll0 = __float2half(x0 - __half2float(hh0));
                    __half ll1 = __float2half(x1 - __half2float(hh1));
                    *(uint32_t*)(Coh + base) = packh2(hh0, hh1);
                    *(uint32_t*)(Col + base) = packh2(ll0, ll1);
                }
            }
        }
    }
}

// ---------------------------------------------------------------------------
// Merged Q/K/V projection kernel (3-term); z selects projection.
// z=0 (Q), z=1 (K): write hi only.  z=2 (V): write hi/lo transposed.
// ---------------------------------------------------------------------------
struct Ptrs3 {
    const __half *Ah, *Al, *Bh, *Bl;
    __half *Oh, *Ol;
};
struct QKVArgs { Ptrs3 p[3]; };

__global__ void __launch_bounds__(256, 2)
qkv_gemm(QKVArgs args)
{
    extern __shared__ __align__(1024) char smem[];
    const uint32_t smem_base = smem_u32_of(smem);

    const int tid = threadIdx.x;
    const int lane = tid & 31;
    const int w = tid >> 5;
    const int wm = w >> 2, wn = w & 3;
    const int z = blockIdx.z;
    const int bm = blockIdx.y * 128;
    const int bn = blockIdx.x * 128;
    const Ptrs3 pp = args.p[z];

    float acc[4][4][4] = {};
    gemm_core<3>(pp.Ah + (long long)bm * EMB, pp.Al + (long long)bm * EMB,
                 pp.Bh + (long long)bn * EMB, pp.Bl + (long long)bn * EMB,
                 EMB, smem_base, acc);

    const int g = lane >> 2, tig = lane & 3;
    const bool doT = (z == 2);
#pragma unroll
    for (int mf = 0; mf < 4; ++mf) {
#pragma unroll
        for (int h2 = 0; h2 < 2; ++h2) {
            const int row = bm + wm * 64 + mf * 16 + g + h2 * 8;
#pragma unroll
            for (int nf = 0; nf < 4; ++nf) {
                const int col = bn + wn * 32 + nf * 8 + 2 * tig;
                const float x0 = acc[mf][nf][h2 * 2 + 0];
                const float x1 = acc[mf][nf][h2 * 2 + 1];
                __half hh0 = __float2half(x0), hh1 = __float2half(x1);
                if (!doT) {
                    // Q/K: hi only
                    *(uint32_t*)(pp.Oh + (long long)row * EMB + col) = packh2(hh0, hh1);
                } else {  // V: transposed hi/lo, dest [b][d=col][l=row&4095]
                    __half ll0 = __float2half(x0 - __half2float(hh0));
                    __half ll1 = __float2half(x1 - __half2float(hh1));
                    const int b = row >> 12, l = row & 4095;
                    const long long ib = (long long)b * (EMB * SEQ) + l;
                    pp.Oh[ib + (long long)col * SEQ] = hh0;
                    pp.Ol[ib + (long long)col * SEQ] = ll0;
                    pp.Oh[ib + (long long)(col + 1) * SEQ] = hh1;
                    pp.Ol[ib + (long long)(col + 1) * SEQ] = ll1;
                }
            }
        }
    }
}

// ---------------------------------------------------------------------------
// Merged fp32 -> (hi, lo) fp16 split conversion over all 7 tensors
// ---------------------------------------------------------------------------
struct CvtArgs {
    const float4* x[7];
    uint2* h[7];
    uint2* l[7];
};
#define BIG4  (NTOK * EMB / 4)   // 2097152
#define W4    (EMB * EMB / 4)    // 65536
#define CVT_TOT (3 * BIG4 + 4 * W4)

__global__ void cvt_all(CvtArgs args)
{
    int idx = blockIdx.x * 256 + threadIdx.x;
    if (idx >= CVT_TOT) return;
    int seg, off;
    if (idx < 3 * BIG4) { seg = idx / BIG4; off = idx - seg * BIG4; }
    else { int j = idx - 3 * BIG4; seg = 3 + j / W4; off = j & (W4 - 1); }
    float4 v = args.x[seg][off];
    __half h0 = __float2half(v.x), h1 = __float2half(v.y);
    __half h2 = __float2half(v.z), h3 = __float2half(v.w);
    __half l0 = __float2half(v.x - __half2float(h0));
    __half l1 = __float2half(v.y - __half2float(h1));
    __half l2 = __float2half(v.z - __half2float(h2));
    __half l3 = __float2half(v.w - __half2float(h3));
    args.h[seg][off] = make_uint2(packh2(h0, h1), packh2(h2, h3));
    args.l[seg][off] = make_uint2(packh2(l0, l1), packh2(l2, l3));
}

// ---------------------------------------------------------------------------
// mask + scale + softmax (vectorized); writes attn weights as fp16 (hi only)
// ---------------------------------------------------------------------------
__global__ void softmax_mask_kernel(const float* __restrict__ E, const int* __restrict__ mask,
                                    __half* __restrict__ Ph)
{
    const long long row = blockIdx.x;
    const float4* e4 = (const float4*)(E + row * (long long)SEQ);
    const int4* m4 = (const int4*)(mask + row * (long long)SEQ);
    uint2* ph2 = (uint2*)(Ph + row * (long long)SEQ);
    const int tid = threadIdx.x;
    const float scale = 0.044194173824159216f;   // 1/sqrt(512)

    float v[16];
    float lmax = -3.0e38f;
#pragma unroll
    for (int i = 0; i < 4; ++i) {
        const int idx = tid + (i << 8);
        float4 x = e4[idx];
        int4 mm = m4[idx];
        v[4*i+0] = (mm.x == 0 ? -1.0e20f : x.x) * scale;
        v[4*i+1] = (mm.y == 0 ? -1.0e20f : x.y) * scale;
        v[4*i+2] = (mm.z == 0 ? -1.0e20f : x.z) * scale;
        v[4*i+3] = (mm.w == 0 ? -1.0e20f : x.w) * scale;
        lmax = fmaxf(fmaxf(fmaxf(v[4*i+0], v[4*i+1]), fmaxf(v[4*i+2], v[4*i+3])), lmax);
    }

    __shared__ float red[8];
#pragma unroll
    for (int o = 16; o > 0; o >>= 1)
        lmax = fmaxf(lmax, __shfl_xor_sync(0xffffffffu, lmax, o));
    if ((tid & 31) == 0) red[tid >> 5] = lmax;
    __syncthreads();
    float rowmax = red[0];
#pragma unroll
    for (int wv = 1; wv < 8; ++wv) rowmax = fmaxf(rowmax, red[wv]);
    __syncthreads();

    float lsum = 0.f;
#pragma unroll
    for (int i = 0; i < 16; ++i) {
        v[i] = __expf(v[i] - rowmax);
        lsum += v[i];
    }
#pragma unroll
    for (int o = 16; o > 0; o >>= 1)
        lsum += __shfl_xor_sync(0xffffffffu, lsum, o);
    if ((tid & 31) == 0) red[tid >> 5] = lsum;
    __syncthreads();
    float rowsum = 0.f;
#pragma unroll
    for (int wv = 0; wv < 8; ++wv) rowsum += red[wv];
    const float inv = 1.0f / rowsum;
#pragma unroll
    for (int i = 0; i < 4; ++i) {
        const int idx = tid + (i << 8);
        ph2[idx] = make_uint2(
            packh2(__float2half(v[4*i+0] * inv), __float2half(v[4*i+1] * inv)),
            packh2(__float2half(v[4*i+2] * inv), __float2half(v[4*i+3] * inv)));
    }
}

// ---------------------------------------------------------------------------
// Launch
// ---------------------------------------------------------------------------
extern "C" void kernel_launch(void* const* d_in, const int* in_sizes, int n_in,
                              void* d_out, int out_size)
{
    (void)in_sizes; (void)n_in; (void)out_size;

    const float* values = (const float*)d_in[0];
    const float* keys   = (const float*)d_in[1];
    const float* query  = (const float*)d_in[2];
    const int*   mask   = (const int*)  d_in[3];
    const float* Wv     = (const float*)d_in[4];
    const float* Wk     = (const float*)d_in[5];
    const float* Wq     = (const float*)d_in[6];
    const float* Wo     = (const float*)d_in[7];
    const float* bo     = (const float*)d_in[8];
    float* out = (float*)d_out;

    __half *vh, *vl, *kh, *kl, *qh, *ql;
    __half *Wvh, *Wvl, *Wkh, *Wkl, *Wqh, *Wql, *Woh, *Wol;
    __half *Qph, *Kph, *VTh, *VTl, *Ph, *AOh, *AOl;
    float* E;
    cudaGetSymbolAddress((void**)&vh, g_vh);   cudaGetSymbolAddress((void**)&vl, g_vl);
    cudaGetSymbolAddress((void**)&kh, g_kh);   cudaGetSymbolAddress((void**)&kl, g_kl);
    cudaGetSymbolAddress((void**)&qh, g_qh);   cudaGetSymbolAddress((void**)&ql, g_ql);
    cudaGetSymbolAddress((void**)&Wvh, g_Wvh); cudaGetSymbolAddress((void**)&Wvl, g_Wvl);
    cudaGetSymbolAddress((void**)&Wkh, g_Wkh); cudaGetSymbolAddress((void**)&Wkl, g_Wkl);
    cudaGetSymbolAddress((void**)&Wqh, g_Wqh); cudaGetSymbolAddress((void**)&Wql, g_Wql);
    cudaGetSymbolAddress((void**)&Woh, g_Woh); cudaGetSymbolAddress((void**)&Wol, g_Wol);
    cudaGetSymbolAddress((void**)&Qph, g_Qph);
    cudaGetSymbolAddress((void**)&Kph, g_Kph);
    cudaGetSymbolAddress((void**)&VTh, g_VTh); cudaGetSymbolAddress((void**)&VTl, g_VTl);
    cudaGetSymbolAddress((void**)&Ph, g_Ph);
    cudaGetSymbolAddress((void**)&AOh, g_AOh); cudaGetSymbolAddress((void**)&AOl, g_AOl);
    cudaGetSymbolAddress((void**)&E, g_E);

    constexpr int SM3 = STAGES * 4 * TILE_B;   // 96 KB
    constexpr int SM2 = STAGES * 3 * TILE_B;   // 72 KB
    constexpr int SM1 = STAGES * 2 * TILE_B;   // 48 KB
    cudaFuncSetAttribute((const void*)mma_gemm<1, 0>, cudaFuncAttributeMaxDynamicSharedMemorySize, SM1);
    cudaFuncSetAttribute((const void*)mma_gemm<2, 1>, cudaFuncAttributeMaxDynamicSharedMemorySize, SM2);
    cudaFuncSetAttribute((const void*)mma_gemm<3, 3>, cudaFuncAttributeMaxDynamicSharedMemorySize, SM3);
    cudaFuncSetAttribute((const void*)qkv_gemm, cudaFuncAttributeMaxDynamicSharedMemorySize, SM3);

    // 1) split inputs + weights into fp16 hi/lo (single launch)
    CvtArgs ca;
    ca.x[0] = (const float4*)query;  ca.h[0] = (uint2*)qh;  ca.l[0] = (uint2*)ql;
    ca.x[1] = (const float4*)keys;   ca.h[1] = (uint2*)kh;  ca.l[1] = (uint2*)kl;
    ca.x[2] = (const float4*)values; ca.h[2] = (uint2*)vh;  ca.l[2] = (uint2*)vl;
    ca.x[3] = (const float4*)Wq;     ca.h[3] = (uint2*)Wqh; ca.l[3] = (uint2*)Wql;
    ca.x[4] = (const float4*)Wk;     ca.h[4] = (uint2*)Wkh; ca.l[4] = (uint2*)Wkl;
    ca.x[5] = (const float4*)Wv;     ca.h[5] = (uint2*)Wvh; ca.l[5] = (uint2*)Wvl;
    ca.x[6] = (const float4*)Wo;     ca.h[6] = (uint2*)Woh; ca.l[6] = (uint2*)Wol;
    cvt_all<<<(CVT_TOT + 255) / 256, 256>>>(ca);

    const dim3 blk(256);
    const long long sQK = (long long)SEQ * EMB;
    const long long sE  = (long long)SEQ * SEQ;

    // 2) merged projections: z=0 Q (hi), z=1 K (hi), z=2 V (transposed hi/lo)
    QKVArgs qa;
    qa.p[0] = { qh, ql, Wqh, Wql, Qph, nullptr };
    qa.p[1] = { kh, kl, Wkh, Wkl, Kph, nullptr };
    qa.p[2] = { vh, vl, Wvh, Wvl, VTh, VTl };
    qkv_gemm<<<dim3(EMB / 128, NTOK / 128, 3), blk, SM3>>>(qa);

    // 3) energy: per-batch [4096,4096] = Qph @ Kph^T, hi-only (fp32 out)
    mma_gemm<1, 0><<<dim3(SEQ / 128, SEQ / 128, NB), blk, SM1>>>(
        Qph, nullptr, Kph, nullptr, E, nullptr, nullptr, nullptr, EMB, SEQ, sQK, sQK, sE);

    // 4) mask + scale + softmax -> attn fp16 (hi only)
    softmax_mask_kernel<<<NB * SEQ, 256>>>(E, mask, Ph);

    // 5) attn @ V: per-batch [4096,512] = Ph @ (VTh + VTl)^T, 2-term (hi/lo out)
    mma_gemm<2, 1><<<dim3(EMB / 128, SEQ / 128, NB), blk, SM2>>>(
        Ph, nullptr, VTh, VTl, nullptr, AOh, AOl, nullptr, SEQ, EMB, sE, sQK, sQK);

    // 6) output projection + bias, 3-term (fp32 out)
    mma_gemm<3, 3><<<dim3(EMB / 128, NTOK / 128, 1), blk, SM3>>>(
        AOh, AOl, Woh, Wol, out, nullptr, nullptr, bo, EMB, EMB, 0, 0, 0);
}

// round 6
// speedup vs baseline: 5.1096x; 1.2233x over previous
#include <cuda_runtime.h>
#include <cuda_fp16.h>
#include <cstdint>

#define NB   4
#define SEQ  4096
#define EMB  512
#define NTOK (NB * SEQ)   // 16384

// ---------------------------------------------------------------------------
// Device scratch
// ---------------------------------------------------------------------------
__device__ __half g_vh[(size_t)NTOK * EMB], g_vl[(size_t)NTOK * EMB];
__device__ __half g_kh[(size_t)NTOK * EMB], g_kl[(size_t)NTOK * EMB];
__device__ __half g_qh[(size_t)NTOK * EMB], g_ql[(size_t)NTOK * EMB];
__device__ __half g_Wvh[EMB * EMB], g_Wvl[EMB * EMB];
__device__ __half g_Wkh[EMB * EMB], g_Wkl[EMB * EMB];
__device__ __half g_Wqh[EMB * EMB], g_Wql[EMB * EMB];
__device__ __half g_Woh[EMB * EMB], g_Wol[EMB * EMB];
__device__ __half g_Qph[(size_t)NTOK * EMB];                        // hi only
__device__ __half g_Kph[(size_t)NTOK * EMB];                        // hi only
__device__ __half g_VTh[(size_t)NTOK * EMB];                        // hi only, [b][d][l]
__device__ __half g_Eh [(size_t)NB * SEQ * SEQ];                    // scaled fp16 energy
__device__ __half g_Ph [(size_t)NB * SEQ * SEQ];                    // hi only
__device__ __half g_AOh[(size_t)NTOK * EMB], g_AOl[(size_t)NTOK * EMB];

// ---------------------------------------------------------------------------
// helpers
// ---------------------------------------------------------------------------
__device__ __forceinline__ uint32_t smem_u32_of(const void* p) {
    uint32_t a;
    asm("{ .reg .u64 t; cvta.to.shared.u64 t, %1; cvt.u32.u64 %0, t; }" : "=r"(a) : "l"(p));
    return a;
}

__device__ __forceinline__ void ldsm4(uint32_t* r, uint32_t addr) {
    asm volatile("ldmatrix.sync.aligned.m8n8.x4.shared.b16 {%0,%1,%2,%3}, [%4];"
                 : "=r"(r[0]), "=r"(r[1]), "=r"(r[2]), "=r"(r[3]) : "r"(addr));
}

__device__ __forceinline__ void mma16816(float* c, const uint32_t* a, const uint32_t* b) {
    asm volatile(
        "mma.sync.aligned.m16n8k16.row.col.f32.f16.f16.f32 "
        "{%0,%1,%2,%3}, {%4,%5,%6,%7}, {%8,%9}, {%0,%1,%2,%3};"
        : "+f"(c[0]), "+f"(c[1]), "+f"(c[2]), "+f"(c[3])
        : "r"(a[0]), "r"(a[1]), "r"(a[2]), "r"(a[3]), "r"(b[0]), "r"(b[1]));
}

#define CP_ASYNC16(dst, src) \
    asm volatile("cp.async.cg.shared.global [%0], [%1], 16;" :: "r"(dst), "l"(src))
#define CP_COMMIT() asm volatile("cp.async.commit_group;")
#define CP_WAIT(n)  asm volatile("cp.async.wait_group %0;" :: "n"(n))

__device__ __forceinline__ uint32_t packh2(__half a, __half b) {
    __half2 h = __halves2half2(a, b);
    return *(uint32_t*)&h;
}

// packed 2-logical-rows-per-128B layout + SW128 swizzle (tile = 128 rows x 32 halves)
__device__ __forceinline__ uint32_t ldoff(int row, int u) {
    uint32_t off = (uint32_t)(((row >> 1) << 7) | ((row & 1) << 6) | (u << 4));
    return off ^ ((off >> 3) & 0x70);
}

#define STAGES 3
#define TILE_B  8192u       // 128 rows * 64B
#define SOFT_SCALE 0.044194173824159216f   // 1/sqrt(512)

// ---------------------------------------------------------------------------
// GEMM core templated on TERMS:
//   TERMS=1: AhBh                      tiles {Ah, Bh}
//   TERMS=2: AhBh + AhBl               tiles {Ah, Bh, Bl}
//   TERMS=3: AhBh + AhBl + AlBh        tiles {Ah, Al, Bh, Bl}
// ---------------------------------------------------------------------------
template <int TERMS>
__device__ __forceinline__ void gemm_core(
    const __half* __restrict__ gAh, const __half* __restrict__ gAl,
    const __half* __restrict__ gBh, const __half* __restrict__ gBl,
    int K, uint32_t smem_base, float acc[4][4][4])
{
    constexpr int A2 = (TERMS == 3) ? 1 : 0;
    constexpr int B2 = (TERMS >= 2) ? 1 : 0;
    constexpr int NT = 2 + A2 + B2;
    constexpr uint32_t STAGE_B = NT * TILE_B;
    constexpr uint32_t T_AH = 0;
    constexpr uint32_t T_AL = TILE_B;
    constexpr uint32_t T_BH = (1 + A2) * TILE_B;
    constexpr uint32_t T_BL = (2 + A2) * TILE_B;

    const int tid = threadIdx.x;
    const int lane = tid & 31;
    const int w = tid >> 5;
    const int wm = w >> 2, wn = w & 3;

    const int ld_row = tid >> 2;
    const int ld_u   = tid & 3;

    const int a_row0 = wm * 64 + (lane & 15);
    const int a_uadd = lane >> 4;
    const int b_row0 = wn * 32 + (lane & 7) + ((lane >> 4) << 3);
    const int b_uadd = (lane >> 3) & 1;

    auto load_chunk = [&](int c) {
        const uint32_t sb = smem_base + (uint32_t)(c % STAGES) * STAGE_B;
        const long long koff = (long long)c * 32;
        const __half* gp[NT];
        gp[0] = gAh + koff;
        if (A2) gp[1] = gAl + koff;
        gp[1 + A2] = gBh + koff;
        if (B2) gp[2 + A2] = gBl + koff;
#pragma unroll
        for (int t = 0; t < NT; ++t) {
#pragma unroll
            for (int i = 0; i < 2; ++i) {
                const int row = ld_row + i * 64;
                const void* g = gp[t] + (long long)row * K + ld_u * 8;
                CP_ASYNC16(sb + t * TILE_B + ldoff(row, ld_u), g);
            }
        }
        CP_COMMIT();
    };

    const int nCh = K >> 5;
#pragma unroll 1
    for (int c = 0; c < STAGES; ++c) load_chunk(c);

#pragma unroll 1
    for (int c = 0; c < nCh; ++c) {
        CP_WAIT(STAGES - 1);
        __syncthreads();
        const uint32_t sb = smem_base + (uint32_t)(c % STAGES) * STAGE_B;

#pragma unroll
        for (int ks = 0; ks < 2; ++ks) {
            uint32_t bH[4][2], bL[4][2];
#pragma unroll
            for (int nh = 0; nh < 2; ++nh) {
                const uint32_t off = ldoff(b_row0 + nh * 16, ks * 2 + b_uadd);
                uint32_t r4[4];
                ldsm4(r4, sb + T_BH + off);
                bH[2 * nh][0] = r4[0]; bH[2 * nh][1] = r4[1];
                bH[2 * nh + 1][0] = r4[2]; bH[2 * nh + 1][1] = r4[3];
                if (B2) {
                    ldsm4(r4, sb + T_BL + off);
                    bL[2 * nh][0] = r4[0]; bL[2 * nh][1] = r4[1];
                    bL[2 * nh + 1][0] = r4[2]; bL[2 * nh + 1][1] = r4[3];
                }
            }
#pragma unroll
            for (int mf = 0; mf < 4; ++mf) {
                const uint32_t off = ldoff(a_row0 + mf * 16, ks * 2 + a_uadd);
                uint32_t aH[4], aL[4];
                ldsm4(aH, sb + T_AH + off);
                if (A2) ldsm4(aL, sb + T_AL + off);
#pragma unroll
                for (int nf = 0; nf < 4; ++nf) {
                    mma16816(acc[mf][nf], aH, bH[nf]);
                    if (B2) mma16816(acc[mf][nf], aH, bL[nf]);
                    if (A2) mma16816(acc[mf][nf], aL, bH[nf]);
                }
            }
        }

        __syncthreads();
        if (c + STAGES < nCh) load_chunk(c + STAGES);
        else CP_COMMIT();
    }
}

// ---------------------------------------------------------------------------
// Generic GEMM kernel.
// EPI: 0 = fp32 C; 1 = hi/lo fp16 row-major; 2 = scaled fp16 (energy);
//      3 = fp32 + bias
// ---------------------------------------------------------------------------
template <int TERMS, int EPI>
__global__ void __launch_bounds__(256, 2)
mma_gemm(const __half* __restrict__ Ah, const __half* __restrict__ Al,
         const __half* __restrict__ Bh, const __half* __restrict__ Bl,
         float* __restrict__ Cf, __half* __restrict__ Coh,
         __half* __restrict__ Col, const float* __restrict__ bias,
         int K, int ldC, long long sA, long long sB, long long sC)
{
    extern __shared__ __align__(1024) char smem[];
    const uint32_t smem_base = smem_u32_of(smem);

    const int tid = threadIdx.x;
    const int lane = tid & 31;
    const int w = tid >> 5;
    const int wm = w >> 2, wn = w & 3;
    const int z = blockIdx.z;
    const int bm = blockIdx.y * 128;
    const int bn = blockIdx.x * 128;

    float acc[4][4][4] = {};
    gemm_core<TERMS>(Ah + (long long)z * sA + (long long)bm * K,
                     (TERMS == 3) ? Al + (long long)z * sA + (long long)bm * K : nullptr,
                     Bh + (long long)z * sB + (long long)bn * K,
                     (TERMS >= 2) ? Bl + (long long)z * sB + (long long)bn * K : nullptr,
                     K, smem_base, acc);

    const int g = lane >> 2, tig = lane & 3;
#pragma unroll
    for (int mf = 0; mf < 4; ++mf) {
#pragma unroll
        for (int h2 = 0; h2 < 2; ++h2) {
            const int row = bm + wm * 64 + mf * 16 + g + h2 * 8;
#pragma unroll
            for (int nf = 0; nf < 4; ++nf) {
                const int col = bn + wn * 32 + nf * 8 + 2 * tig;
                const float x0 = acc[mf][nf][h2 * 2 + 0];
                const float x1 = acc[mf][nf][h2 * 2 + 1];
                if (EPI == 0) {
                    *(float2*)(Cf + (long long)z * sC + (long long)row * ldC + col) =
                        make_float2(x0, x1);
                } else if (EPI == 3) {
                    *(float2*)(Cf + (long long)z * sC + (long long)row * ldC + col) =
                        make_float2(x0 + bias[col], x1 + bias[col + 1]);
                } else if (EPI == 2) {
                    const long long base = (long long)z * sC + (long long)row * ldC + col;
                    *(uint32_t*)(Coh + base) =
                        packh2(__float2half(x0 * SOFT_SCALE), __float2half(x1 * SOFT_SCALE));
                } else {
                    const long long base = (long long)z * sC + (long long)row * ldC + col;
                    __half hh0 = __float2half(x0), hh1 = __float2half(x1);
                    __half ll0 = __float2half(x0 - __half2float(hh0));
                    __half ll1 = __float2half(x1 - __half2float(hh1));
                    *(uint32_t*)(Coh + base) = packh2(hh0, hh1);
                    *(uint32_t*)(Col + base) = packh2(ll0, ll1);
                }
            }
        }
    }
}

// ---------------------------------------------------------------------------
// Merged Q/K/V projection kernel (3-term); z selects projection.
// z=0 (Q), z=1 (K): write hi only.  z=2 (V): write hi only, transposed.
// ---------------------------------------------------------------------------
struct Ptrs3 {
    const __half *Ah, *Al, *Bh, *Bl;
    __half *Oh;
};
struct QKVArgs { Ptrs3 p[3]; };

__global__ void __launch_bounds__(256, 2)
qkv_gemm(QKVArgs args)
{
    extern __shared__ __align__(1024) char smem[];
    const uint32_t smem_base = smem_u32_of(smem);

    const int tid = threadIdx.x;
    const int lane = tid & 31;
    const int w = tid >> 5;
    const int wm = w >> 2, wn = w & 3;
    const int z = blockIdx.z;
    const int bm = blockIdx.y * 128;
    const int bn = blockIdx.x * 128;
    const Ptrs3 pp = args.p[z];

    float acc[4][4][4] = {};
    gemm_core<3>(pp.Ah + (long long)bm * EMB, pp.Al + (long long)bm * EMB,
                 pp.Bh + (long long)bn * EMB, pp.Bl + (long long)bn * EMB,
                 EMB, smem_base, acc);

    const int g = lane >> 2, tig = lane & 3;
    const bool doT = (z == 2);
#pragma unroll
    for (int mf = 0; mf < 4; ++mf) {
#pragma unroll
        for (int h2 = 0; h2 < 2; ++h2) {
            const int row = bm + wm * 64 + mf * 16 + g + h2 * 8;
#pragma unroll
            for (int nf = 0; nf < 4; ++nf) {
                const int col = bn + wn * 32 + nf * 8 + 2 * tig;
                const float x0 = acc[mf][nf][h2 * 2 + 0];
                const float x1 = acc[mf][nf][h2 * 2 + 1];
                __half hh0 = __float2half(x0), hh1 = __float2half(x1);
                if (!doT) {
                    *(uint32_t*)(pp.Oh + (long long)row * EMB + col) = packh2(hh0, hh1);
                } else {  // V: transposed hi, dest [b][d=col][l=row&4095]
                    const int b = row >> 12, l = row & 4095;
                    const long long ib = (long long)b * (EMB * SEQ) + l;
                    pp.Oh[ib + (long long)col * SEQ] = hh0;
                    pp.Oh[ib + (long long)(col + 1) * SEQ] = hh1;
                }
            }
        }
    }
}

// ---------------------------------------------------------------------------
// Merged fp32 -> (hi, lo) fp16 split conversion over all 7 tensors
// ---------------------------------------------------------------------------
struct CvtArgs {
    const float4* x[7];
    uint2* h[7];
    uint2* l[7];
};
#define BIG4  (NTOK * EMB / 4)   // 2097152
#define W4    (EMB * EMB / 4)    // 65536
#define CVT_TOT (3 * BIG4 + 4 * W4)

__global__ void cvt_all(CvtArgs args)
{
    int idx = blockIdx.x * 256 + threadIdx.x;
    if (idx >= CVT_TOT) return;
    int seg, off;
    if (idx < 3 * BIG4) { seg = idx / BIG4; off = idx - seg * BIG4; }
    else { int j = idx - 3 * BIG4; seg = 3 + j / W4; off = j & (W4 - 1); }
    float4 v = args.x[seg][off];
    __half h0 = __float2half(v.x), h1 = __float2half(v.y);
    __half h2 = __float2half(v.z), h3 = __float2half(v.w);
    __half l0 = __float2half(v.x - __half2float(h0));
    __half l1 = __float2half(v.y - __half2float(h1));
    __half l2 = __float2half(v.z - __half2float(h2));
    __half l3 = __float2half(v.w - __half2float(h3));
    args.h[seg][off] = make_uint2(packh2(h0, h1), packh2(h2, h3));
    args.l[seg][off] = make_uint2(packh2(l0, l1), packh2(l2, l3));
}

// ---------------------------------------------------------------------------
// mask + softmax over scaled fp16 energy; writes attn weights as fp16 (hi)
// Each thread handles 2 groups of 8 contiguous halves.
// ---------------------------------------------------------------------------
__global__ void softmax_mask_kernel(const __half* __restrict__ Eh, const int* __restrict__ mask,
                                    __half* __restrict__ Ph)
{
    const long long row = blockIdx.x;
    const uint4* e8 = (const uint4*)(Eh + row * (long long)SEQ);
    const int4* m4 = (const int4*)(mask + row * (long long)SEQ);
    uint4* p8 = (uint4*)(Ph + row * (long long)SEQ);
    const int tid = threadIdx.x;

    float v[16];
    float lmax = -3.0e38f;
#pragma unroll
    for (int i = 0; i < 2; ++i) {
        const int gi = tid + (i << 8);          // group of 8 halves
        const uint4 ev = e8[gi];
        const int4 m0 = m4[2 * gi];
        const int4 m1 = m4[2 * gi + 1];
        const uint32_t ew[4] = {ev.x, ev.y, ev.z, ev.w};
        const int mm[8] = {m0.x, m0.y, m0.z, m0.w, m1.x, m1.y, m1.z, m1.w};
#pragma unroll
        for (int j = 0; j < 4; ++j) {
            const float2 f2 = __half22float2(*(const __half2*)&ew[j]);
            const float a = (mm[2 * j] == 0) ? -1.0e20f : f2.x;
            const float b = (mm[2 * j + 1] == 0) ? -1.0e20f : f2.y;
            v[8 * i + 2 * j] = a;
            v[8 * i + 2 * j + 1] = b;
            lmax = fmaxf(lmax, fmaxf(a, b));
        }
    }

    __shared__ float red[8];
#pragma unroll
    for (int o = 16; o > 0; o >>= 1)
        lmax = fmaxf(lmax, __shfl_xor_sync(0xffffffffu, lmax, o));
    if ((tid & 31) == 0) red[tid >> 5] = lmax;
    __syncthreads();
    float rowmax = red[0];
#pragma unroll
    for (int wv = 1; wv < 8; ++wv) rowmax = fmaxf(rowmax, red[wv]);
    __syncthreads();

    float lsum = 0.f;
#pragma unroll
    for (int i = 0; i < 16; ++i) {
        v[i] = __expf(v[i] - rowmax);
        lsum += v[i];
    }
#pragma unroll
    for (int o = 16; o > 0; o >>= 1)
        lsum += __shfl_xor_sync(0xffffffffu, lsum, o);
    if ((tid & 31) == 0) red[tid >> 5] = lsum;
    __syncthreads();
    float rowsum = 0.f;
#pragma unroll
    for (int wv = 0; wv < 8; ++wv) rowsum += red[wv];
    const float inv = 1.0f / rowsum;

#pragma unroll
    for (int i = 0; i < 2; ++i) {
        const int gi = tid + (i << 8);
        uint4 o;
        o.x = packh2(__float2half(v[8*i+0] * inv), __float2half(v[8*i+1] * inv));
        o.y = packh2(__float2half(v[8*i+2] * inv), __float2half(v[8*i+3] * inv));
        o.z = packh2(__float2half(v[8*i+4] * inv), __float2half(v[8*i+5] * inv));
        o.w = packh2(__float2half(v[8*i+6] * inv), __float2half(v[8*i+7] * inv));
        p8[gi] = o;
    }
}

// ---------------------------------------------------------------------------
// Launch
// ---------------------------------------------------------------------------
extern "C" void kernel_launch(void* const* d_in, const int* in_sizes, int n_in,
                              void* d_out, int out_size)
{
    (void)in_sizes; (void)n_in; (void)out_size;

    const float* values = (const float*)d_in[0];
    const float* keys   = (const float*)d_in[1];
    const float* query  = (const float*)d_in[2];
    const int*   mask   = (const int*)  d_in[3];
    const float* Wv     = (const float*)d_in[4];
    const float* Wk     = (const float*)d_in[5];
    const float* Wq     = (const float*)d_in[6];
    const float* Wo     = (const float*)d_in[7];
    const float* bo     = (const float*)d_in[8];
    float* out = (float*)d_out;

    __half *vh, *vl, *kh, *kl, *qh, *ql;
    __half *Wvh, *Wvl, *Wkh, *Wkl, *Wqh, *Wql, *Woh, *Wol;
    __half *Qph, *Kph, *VTh, *Eh, *Ph, *AOh, *AOl;
    cudaGetSymbolAddress((void**)&vh, g_vh);   cudaGetSymbolAddress((void**)&vl, g_vl);
    cudaGetSymbolAddress((void**)&kh, g_kh);   cudaGetSymbolAddress((void**)&kl, g_kl);
    cudaGetSymbolAddress((void**)&qh, g_qh);   cudaGetSymbolAddress((void**)&ql, g_ql);
    cudaGetSymbolAddress((void**)&Wvh, g_Wvh); cudaGetSymbolAddress((void**)&Wvl, g_Wvl);
    cudaGetSymbolAddress((void**)&Wkh, g_Wkh); cudaGetSymbolAddress((void**)&Wkl, g_Wkl);
    cudaGetSymbolAddress((void**)&Wqh, g_Wqh); cudaGetSymbolAddress((void**)&Wql, g_Wql);
    cudaGetSymbolAddress((void**)&Woh, g_Woh); cudaGetSymbolAddress((void**)&Wol, g_Wol);
    cudaGetSymbolAddress((void**)&Qph, g_Qph);
    cudaGetSymbolAddress((void**)&Kph, g_Kph);
    cudaGetSymbolAddress((void**)&VTh, g_VTh);
    cudaGetSymbolAddress((void**)&Eh, g_Eh);
    cudaGetSymbolAddress((void**)&Ph, g_Ph);
    cudaGetSymbolAddress((void**)&AOh, g_AOh); cudaGetSymbolAddress((void**)&AOl, g_AOl);

    constexpr int SM3 = STAGES * 4 * TILE_B;   // 96 KB
    constexpr int SM1 = STAGES * 2 * TILE_B;   // 48 KB
    cudaFuncSetAttribute((const void*)mma_gemm<1, 2>, cudaFuncAttributeMaxDynamicSharedMemorySize, SM1);
    cudaFuncSetAttribute((const void*)mma_gemm<1, 1>, cudaFuncAttributeMaxDynamicSharedMemorySize, SM1);
    cudaFuncSetAttribute((const void*)mma_gemm<3, 3>, cudaFuncAttributeMaxDynamicSharedMemorySize, SM3);
    cudaFuncSetAttribute((const void*)qkv_gemm, cudaFuncAttributeMaxDynamicSharedMemorySize, SM3);

    // 1) split inputs + weights into fp16 hi/lo (single launch)
    CvtArgs ca;
    ca.x[0] = (const float4*)query;  ca.h[0] = (uint2*)qh;  ca.l[0] = (uint2*)ql;
    ca.x[1] = (const float4*)keys;   ca.h[1] = (uint2*)kh;  ca.l[1] = (uint2*)kl;
    ca.x[2] = (const float4*)values; ca.h[2] = (uint2*)vh;  ca.l[2] = (uint2*)vl;
    ca.x[3] = (const float4*)Wq;     ca.h[3] = (uint2*)Wqh; ca.l[3] = (uint2*)Wql;
    ca.x[4] = (const float4*)Wk;     ca.h[4] = (uint2*)Wkh; ca.l[4] = (uint2*)Wkl;
    ca.x[5] = (const float4*)Wv;     ca.h[5] = (uint2*)Wvh; ca.l[5] = (uint2*)Wvl;
    ca.x[6] = (const float4*)Wo;     ca.h[6] = (uint2*)Woh; ca.l[6] = (uint2*)Wol;
    cvt_all<<<(CVT_TOT + 255) / 256, 256>>>(ca);

    const dim3 blk(256);
    const long long sQK = (long long)SEQ * EMB;
    const long long sE  = (long long)SEQ * SEQ;

    // 2) merged projections: z=0 Q (hi), z=1 K (hi), z=2 V (transposed hi)
    QKVArgs qa;
    qa.p[0] = { qh, ql, Wqh, Wql, Qph };
    qa.p[1] = { kh, kl, Wkh, Wkl, Kph };
    qa.p[2] = { vh, vl, Wvh, Wvl, VTh };
    qkv_gemm<<<dim3(EMB / 128, NTOK / 128, 3), blk, SM3>>>(qa);

    // 3) energy: per-batch [4096,4096] = Qph @ Kph^T, hi-only -> scaled fp16
    mma_gemm<1, 2><<<dim3(SEQ / 128, SEQ / 128, NB), blk, SM1>>>(
        Qph, nullptr, Kph, nullptr, nullptr, Eh, nullptr, nullptr, EMB, SEQ, sQK, sQK, sE);

    // 4) mask + softmax -> attn fp16 (hi only)
    softmax_mask_kernel<<<NB * SEQ, 256>>>(Eh, mask, Ph);

    // 5) attn @ V: per-batch [4096,512] = Ph @ VTh^T, 1-term (hi/lo out)
    mma_gemm<1, 1><<<dim3(EMB / 128, SEQ / 128, NB), blk, SM1>>>(
        Ph, nullptr, VTh, nullptr, nullptr, AOh, AOl, nullptr, SEQ, EMB, sE, sQK, sQK);

    // 6) output projection + bias, 3-term (fp32 out)
    mma_gemm<3, 3><<<dim3(EMB / 128, NTOK / 128, 1), blk, SM3>>>(
        AOh, AOl, Woh, Wol, out, nullptr, nullptr, bo, EMB, EMB, 0, 0, 0);
}

// round 7
// speedup vs baseline: 5.5607x; 1.0883x over previous
#include <cuda_runtime.h>
#include <cuda_fp16.h>
#include <cstdint>

#define NB   4
#define SEQ  4096
#define EMB  512
#define NTOK (NB * SEQ)   // 16384

// ---------------------------------------------------------------------------
// Device scratch
// ---------------------------------------------------------------------------
__device__ __half g_vh[(size_t)NTOK * EMB], g_vl[(size_t)NTOK * EMB];
__device__ __half g_kh[(size_t)NTOK * EMB], g_kl[(size_t)NTOK * EMB];
__device__ __half g_qh[(size_t)NTOK * EMB], g_ql[(size_t)NTOK * EMB];
__device__ __half g_Wvh[EMB * EMB], g_Wvl[EMB * EMB];
__device__ __half g_Wkh[EMB * EMB], g_Wkl[EMB * EMB];
__device__ __half g_Wqh[EMB * EMB], g_Wql[EMB * EMB];
__device__ __half g_Woh[EMB * EMB], g_Wol[EMB * EMB];
__device__ __half g_Qph[(size_t)NTOK * EMB];                        // hi only
__device__ __half g_Kph[(size_t)NTOK * EMB];                        // hi only
__device__ __half g_VTh[(size_t)NTOK * EMB];                        // hi only, [b][d][l]
__device__ __half g_Eh [(size_t)NB * SEQ * SEQ];                    // scaled fp16 energy
__device__ __half g_Ph [(size_t)NB * SEQ * SEQ];                    // hi only
__device__ __half g_AOh[(size_t)NTOK * EMB];                        // hi only

// ---------------------------------------------------------------------------
// helpers
// ---------------------------------------------------------------------------
__device__ __forceinline__ uint32_t smem_u32_of(const void* p) {
    uint32_t a;
    asm("{ .reg .u64 t; cvta.to.shared.u64 t, %1; cvt.u32.u64 %0, t; }" : "=r"(a) : "l"(p));
    return a;
}

__device__ __forceinline__ void ldsm4(uint32_t* r, uint32_t addr) {
    asm volatile("ldmatrix.sync.aligned.m8n8.x4.shared.b16 {%0,%1,%2,%3}, [%4];"
                 : "=r"(r[0]), "=r"(r[1]), "=r"(r[2]), "=r"(r[3]) : "r"(addr));
}

__device__ __forceinline__ void mma16816(float* c, const uint32_t* a, const uint32_t* b) {
    asm volatile(
        "mma.sync.aligned.m16n8k16.row.col.f32.f16.f16.f32 "
        "{%0,%1,%2,%3}, {%4,%5,%6,%7}, {%8,%9}, {%0,%1,%2,%3};"
        : "+f"(c[0]), "+f"(c[1]), "+f"(c[2]), "+f"(c[3])
        : "r"(a[0]), "r"(a[1]), "r"(a[2]), "r"(a[3]), "r"(b[0]), "r"(b[1]));
}

#define CP_ASYNC16(dst, src) \
    asm volatile("cp.async.cg.shared.global [%0], [%1], 16;" :: "r"(dst), "l"(src))
#define CP_COMMIT() asm volatile("cp.async.commit_group;")
#define CP_WAIT(n)  asm volatile("cp.async.wait_group %0;" :: "n"(n))

__device__ __forceinline__ uint32_t packh2(__half a, __half b) {
    __half2 h = __halves2half2(a, b);
    return *(uint32_t*)&h;
}

#define STAGES 3
#define SOFT_SCALE 0.044194173824159216f   // 1/sqrt(512)

// smem offset helpers
// CHUNK=32: packed 2-rows-per-128B (tile 128 x 32 halves = 8 KB), u in 0..3
// CHUNK=64: plain 128B rows        (tile 128 x 64 halves = 16 KB), u in 0..7
template <int CHUNK>
__device__ __forceinline__ uint32_t foff(int row, int u) {
    uint32_t off;
    if (CHUNK == 64) off = (uint32_t)(row * 128 + u * 16);
    else             off = (uint32_t)(((row >> 1) << 7) | ((row & 1) << 6) | (u << 4));
    return off ^ ((off >> 3) & 0x70);
}

// ---------------------------------------------------------------------------
// GEMM core templated on TERMS and CHUNK:
//   TERMS=1: AhBh            tiles {Ah, Bh}
//   TERMS=2: AhBh + AhBl     tiles {Ah, Bh, Bl}
//   TERMS=3: AhBh+AhBl+AlBh  tiles {Ah, Al, Bh, Bl}
// ---------------------------------------------------------------------------
template <int TERMS, int CHUNK>
__device__ __forceinline__ void gemm_core(
    const __half* __restrict__ gAh, const __half* __restrict__ gAl,
    const __half* __restrict__ gBh, const __half* __restrict__ gBl,
    int K, uint32_t smem_base, float acc[4][4][4])
{
    constexpr int A2 = (TERMS == 3) ? 1 : 0;
    constexpr int B2 = (TERMS >= 2) ? 1 : 0;
    constexpr int NT = 2 + A2 + B2;
    constexpr uint32_t TB = (CHUNK == 64) ? 16384u : 8192u;
    constexpr uint32_t STAGE_B = NT * TB;
    constexpr uint32_t T_AH = 0;
    constexpr uint32_t T_AL = TB;
    constexpr uint32_t T_BH = (1 + A2) * TB;
    constexpr uint32_t T_BL = (2 + A2) * TB;
    constexpr int KS_N = CHUNK / 16;     // ks iterations per chunk

    const int tid = threadIdx.x;
    const int lane = tid & 31;
    const int w = tid >> 5;
    const int wm = w >> 2, wn = w & 3;

    // global->smem thread mapping
    const int ld_row = (CHUNK == 64) ? (tid >> 3) : (tid >> 2);
    const int ld_u   = (CHUNK == 64) ? (tid & 7) : (tid & 3);
    constexpr int LD_IT   = (CHUNK == 64) ? 4 : 2;
    constexpr int LD_STEP = (CHUNK == 64) ? 32 : 64;

    const int a_row0 = wm * 64 + (lane & 15);
    const int a_uadd = lane >> 4;
    const int b_row0 = wn * 32 + (lane & 7) + ((lane >> 4) << 3);
    const int b_uadd = (lane >> 3) & 1;

    auto load_chunk = [&](int c) {
        const uint32_t sb = smem_base + (uint32_t)(c % STAGES) * STAGE_B;
        const long long koff = (long long)c * CHUNK;
        const __half* gp[NT];
        gp[0] = gAh + koff;
        if (A2) gp[1] = gAl + koff;
        gp[1 + A2] = gBh + koff;
        if (B2) gp[2 + A2] = gBl + koff;
#pragma unroll
        for (int t = 0; t < NT; ++t) {
#pragma unroll
            for (int i = 0; i < LD_IT; ++i) {
                const int row = ld_row + i * LD_STEP;
                const void* g = gp[t] + (long long)row * K + ld_u * 8;
                CP_ASYNC16(sb + t * TB + foff<CHUNK>(row, ld_u), g);
            }
        }
        CP_COMMIT();
    };

    const int nCh = K / CHUNK;
#pragma unroll 1
    for (int c = 0; c < STAGES; ++c) load_chunk(c);

#pragma unroll 1
    for (int c = 0; c < nCh; ++c) {
        CP_WAIT(STAGES - 1);
        __syncthreads();
        const uint32_t sb = smem_base + (uint32_t)(c % STAGES) * STAGE_B;

#pragma unroll
        for (int ks = 0; ks < KS_N; ++ks) {
            uint32_t bH[4][2], bL[4][2];
#pragma unroll
            for (int nh = 0; nh < 2; ++nh) {
                const uint32_t off = foff<CHUNK>(b_row0 + nh * 16, ks * 2 + b_uadd);
                uint32_t r4[4];
                ldsm4(r4, sb + T_BH + off);
                bH[2 * nh][0] = r4[0]; bH[2 * nh][1] = r4[1];
                bH[2 * nh + 1][0] = r4[2]; bH[2 * nh + 1][1] = r4[3];
                if (B2) {
                    ldsm4(r4, sb + T_BL + off);
                    bL[2 * nh][0] = r4[0]; bL[2 * nh][1] = r4[1];
                    bL[2 * nh + 1][0] = r4[2]; bL[2 * nh + 1][1] = r4[3];
                }
            }
#pragma unroll
            for (int mf = 0; mf < 4; ++mf) {
                const uint32_t off = foff<CHUNK>(a_row0 + mf * 16, ks * 2 + a_uadd);
                uint32_t aH[4], aL[4];
                ldsm4(aH, sb + T_AH + off);
                if (A2) ldsm4(aL, sb + T_AL + off);
#pragma unroll
                for (int nf = 0; nf < 4; ++nf) {
                    mma16816(acc[mf][nf], aH, bH[nf]);
                    if (B2) mma16816(acc[mf][nf], aH, bL[nf]);
                    if (A2) mma16816(acc[mf][nf], aL, bH[nf]);
                }
            }
        }

        __syncthreads();
        if (c + STAGES < nCh) load_chunk(c + STAGES);
        else CP_COMMIT();
    }
}

// ---------------------------------------------------------------------------
// Generic GEMM kernel.
// EPI: 2 = scaled fp16; 3 = fp32 + bias; 4 = fp16 hi only
// ---------------------------------------------------------------------------
template <int TERMS, int EPI, int CHUNK>
__global__ void __launch_bounds__(256, 2)
mma_gemm(const __half* __restrict__ Ah, const __half* __restrict__ Al,
         const __half* __restrict__ Bh, const __half* __restrict__ Bl,
         float* __restrict__ Cf, __half* __restrict__ Coh,
         const float* __restrict__ bias,
         int K, int ldC, long long sA, long long sB, long long sC)
{
    extern __shared__ __align__(1024) char smem[];
    const uint32_t smem_base = smem_u32_of(smem);

    const int tid = threadIdx.x;
    const int lane = tid & 31;
    const int w = tid >> 5;
    const int wm = w >> 2, wn = w & 3;
    const int z = blockIdx.z;
    const int bm = blockIdx.y * 128;
    const int bn = blockIdx.x * 128;

    float acc[4][4][4] = {};
    gemm_core<TERMS, CHUNK>(
        Ah + (long long)z * sA + (long long)bm * K,
        (TERMS == 3) ? Al + (long long)z * sA + (long long)bm * K : nullptr,
        Bh + (long long)z * sB + (long long)bn * K,
        (TERMS >= 2) ? Bl + (long long)z * sB + (long long)bn * K : nullptr,
        K, smem_base, acc);

    const int g = lane >> 2, tig = lane & 3;
#pragma unroll
    for (int mf = 0; mf < 4; ++mf) {
#pragma unroll
        for (int h2 = 0; h2 < 2; ++h2) {
            const int row = bm + wm * 64 + mf * 16 + g + h2 * 8;
#pragma unroll
            for (int nf = 0; nf < 4; ++nf) {
                const int col = bn + wn * 32 + nf * 8 + 2 * tig;
                const float x0 = acc[mf][nf][h2 * 2 + 0];
                const float x1 = acc[mf][nf][h2 * 2 + 1];
                if (EPI == 3) {
                    *(float2*)(Cf + (long long)z * sC + (long long)row * ldC + col) =
                        make_float2(x0 + bias[col], x1 + bias[col + 1]);
                } else if (EPI == 2) {
                    const long long base = (long long)z * sC + (long long)row * ldC + col;
                    *(uint32_t*)(Coh + base) =
                        packh2(__float2half(x0 * SOFT_SCALE), __float2half(x1 * SOFT_SCALE));
                } else {  // EPI == 4: fp16 hi only
                    const long long base = (long long)z * sC + (long long)row * ldC + col;
                    *(uint32_t*)(Coh + base) = packh2(__float2half(x0), __float2half(x1));
                }
            }
        }
    }
}

// ---------------------------------------------------------------------------
// Merged Q/K/V projection kernel (3-term, chunk 32); z selects projection.
// z=0 (Q), z=1 (K): write hi only.  z=2 (V): write hi only, transposed.
// ---------------------------------------------------------------------------
struct Ptrs3 {
    const __half *Ah, *Al, *Bh, *Bl;
    __half *Oh;
};
struct QKVArgs { Ptrs3 p[3]; };

__global__ void __launch_bounds__(256, 2)
qkv_gemm(QKVArgs args)
{
    extern __shared__ __align__(1024) char smem[];
    const uint32_t smem_base = smem_u32_of(smem);

    const int tid = threadIdx.x;
    const int lane = tid & 31;
    const int w = tid >> 5;
    const int wm = w >> 2, wn = w & 3;
    const int z = blockIdx.z;
    const int bm = blockIdx.y * 128;
    const int bn = blockIdx.x * 128;
    const Ptrs3 pp = args.p[z];

    float acc[4][4][4] = {};
    gemm_core<3, 32>(pp.Ah + (long long)bm * EMB, pp.Al + (long long)bm * EMB,
                     pp.Bh + (long long)bn * EMB, pp.Bl + (long long)bn * EMB,
                     EMB, smem_base, acc);

    const int g = lane >> 2, tig = lane & 3;
    const bool doT = (z == 2);
#pragma unroll
    for (int mf = 0; mf < 4; ++mf) {
#pragma unroll
        for (int h2 = 0; h2 < 2; ++h2) {
            const int row = bm + wm * 64 + mf * 16 + g + h2 * 8;
#pragma unroll
            for (int nf = 0; nf < 4; ++nf) {
                const int col = bn + wn * 32 + nf * 8 + 2 * tig;
                const float x0 = acc[mf][nf][h2 * 2 + 0];
                const float x1 = acc[mf][nf][h2 * 2 + 1];
                __half hh0 = __float2half(x0), hh1 = __float2half(x1);
                if (!doT) {
                    *(uint32_t*)(pp.Oh + (long long)row * EMB + col) = packh2(hh0, hh1);
                } else {  // V: transposed hi, dest [b][d=col][l=row&4095]
                    const int b = row >> 12, l = row & 4095;
                    const long long ib = (long long)b * (EMB * SEQ) + l;
                    pp.Oh[ib + (long long)col * SEQ] = hh0;
                    pp.Oh[ib + (long long)(col + 1) * SEQ] = hh1;
                }
            }
        }
    }
}

// ---------------------------------------------------------------------------
// Merged fp32 -> (hi, lo) fp16 split conversion over all 7 tensors
// ---------------------------------------------------------------------------
struct CvtArgs {
    const float4* x[7];
    uint2* h[7];
    uint2* l[7];
};
#define BIG4  (NTOK * EMB / 4)   // 2097152
#define W4    (EMB * EMB / 4)    // 65536
#define CVT_TOT (3 * BIG4 + 4 * W4)

__global__ void cvt_all(CvtArgs args)
{
    int idx = blockIdx.x * 256 + threadIdx.x;
    if (idx >= CVT_TOT) return;
    int seg, off;
    if (idx < 3 * BIG4) { seg = idx / BIG4; off = idx - seg * BIG4; }
    else { int j = idx - 3 * BIG4; seg = 3 + j / W4; off = j & (W4 - 1); }
    float4 v = args.x[seg][off];
    __half h0 = __float2half(v.x), h1 = __float2half(v.y);
    __half h2 = __float2half(v.z), h3 = __float2half(v.w);
    __half l0 = __float2half(v.x - __half2float(h0));
    __half l1 = __float2half(v.y - __half2float(h1));
    __half l2 = __float2half(v.z - __half2float(h2));
    __half l3 = __float2half(v.w - __half2float(h3));
    args.h[seg][off] = make_uint2(packh2(h0, h1), packh2(h2, h3));
    args.l[seg][off] = make_uint2(packh2(l0, l1), packh2(l2, l3));
}

// ---------------------------------------------------------------------------
// mask + softmax over scaled fp16 energy; writes attn weights as fp16 (hi)
// ---------------------------------------------------------------------------
__global__ void softmax_mask_kernel(const __half* __restrict__ Eh, const int* __restrict__ mask,
                                    __half* __restrict__ Ph)
{
    const long long row = blockIdx.x;
    const uint4* e8 = (const uint4*)(Eh + row * (long long)SEQ);
    const int4* m4 = (const int4*)(mask + row * (long long)SEQ);
    uint4* p8 = (uint4*)(Ph + row * (long long)SEQ);
    const int tid = threadIdx.x;

    float v[16];
    float lmax = -3.0e38f;
#pragma unroll
    for (int i = 0; i < 2; ++i) {
        const int gi = tid + (i << 8);          // group of 8 halves
        const uint4 ev = e8[gi];
        const int4 m0 = m4[2 * gi];
        const int4 m1 = m4[2 * gi + 1];
        const uint32_t ew[4] = {ev.x, ev.y, ev.z, ev.w};
        const int mm[8] = {m0.x, m0.y, m0.z, m0.w, m1.x, m1.y, m1.z, m1.w};
#pragma unroll
        for (int j = 0; j < 4; ++j) {
            const float2 f2 = __half22float2(*(const __half2*)&ew[j]);
            const float a = (mm[2 * j] == 0) ? -1.0e20f : f2.x;
            const float b = (mm[2 * j + 1] == 0) ? -1.0e20f : f2.y;
            v[8 * i + 2 * j] = a;
            v[8 * i + 2 * j + 1] = b;
            lmax = fmaxf(lmax, fmaxf(a, b));
        }
    }

    __shared__ float red[8];
#pragma unroll
    for (int o = 16; o > 0; o >>= 1)
        lmax = fmaxf(lmax, __shfl_xor_sync(0xffffffffu, lmax, o));
    if ((tid & 31) == 0) red[tid >> 5] = lmax;
    __syncthreads();
    float rowmax = red[0];
#pragma unroll
    for (int wv = 1; wv < 8; ++wv) rowmax = fmaxf(rowmax, red[wv]);
    __syncthreads();

    float lsum = 0.f;
#pragma unroll
    for (int i = 0; i < 16; ++i) {
        v[i] = __expf(v[i] - rowmax);
        lsum += v[i];
    }
#pragma unroll
    for (int o = 16; o > 0; o >>= 1)
        lsum += __shfl_xor_sync(0xffffffffu, lsum, o);
    if ((tid & 31) == 0) red[tid >> 5] = lsum;
    __syncthreads();
    float rowsum = 0.f;
#pragma unroll
    for (int wv = 0; wv < 8; ++wv) rowsum += red[wv];
    const float inv = 1.0f / rowsum;

#pragma unroll
    for (int i = 0; i < 2; ++i) {
        const int gi = tid + (i << 8);
        uint4 o;
        o.x = packh2(__float2half(v[8*i+0] * inv), __float2half(v[8*i+1] * inv));
        o.y = packh2(__float2half(v[8*i+2] * inv), __float2half(v[8*i+3] * inv));
        o.z = packh2(__float2half(v[8*i+4] * inv), __float2half(v[8*i+5] * inv));
        o.w = packh2(__float2half(v[8*i+6] * inv), __float2half(v[8*i+7] * inv));
        p8[gi] = o;
    }
}

// ---------------------------------------------------------------------------
// Launch
// ---------------------------------------------------------------------------
extern "C" void kernel_launch(void* const* d_in, const int* in_sizes, int n_in,
                              void* d_out, int out_size)
{
    (void)in_sizes; (void)n_in; (void)out_size;

    const float* values = (const float*)d_in[0];
    const float* keys   = (const float*)d_in[1];
    const float* query  = (const float*)d_in[2];
    const int*   mask   = (const int*)  d_in[3];
    const float* Wv     = (const float*)d_in[4];
    const float* Wk     = (const float*)d_in[5];
    const float* Wq     = (const float*)d_in[6];
    const float* Wo     = (const float*)d_in[7];
    const float* bo     = (const float*)d_in[8];
    float* out = (float*)d_out;

    __half *vh, *vl, *kh, *kl, *qh, *ql;
    __half *Wvh, *Wvl, *Wkh, *Wkl, *Wqh, *Wql, *Woh, *Wol;
    __half *Qph, *Kph, *VTh, *Eh, *Ph, *AOh;
    cudaGetSymbolAddress((void**)&vh, g_vh);   cudaGetSymbolAddress((void**)&vl, g_vl);
    cudaGetSymbolAddress((void**)&kh, g_kh);   cudaGetSymbolAddress((void**)&kl, g_kl);
    cudaGetSymbolAddress((void**)&qh, g_qh);   cudaGetSymbolAddress((void**)&ql, g_ql);
    cudaGetSymbolAddress((void**)&Wvh, g_Wvh); cudaGetSymbolAddress((void**)&Wvl, g_Wvl);
    cudaGetSymbolAddress((void**)&Wkh, g_Wkh); cudaGetSymbolAddress((void**)&Wkl, g_Wkl);
    cudaGetSymbolAddress((void**)&Wqh, g_Wqh); cudaGetSymbolAddress((void**)&Wql, g_Wql);
    cudaGetSymbolAddress((void**)&Woh, g_Woh); cudaGetSymbolAddress((void**)&Wol, g_Wol);
    cudaGetSymbolAddress((void**)&Qph, g_Qph);
    cudaGetSymbolAddress((void**)&Kph, g_Kph);
    cudaGetSymbolAddress((void**)&VTh, g_VTh);
    cudaGetSymbolAddress((void**)&Eh, g_Eh);
    cudaGetSymbolAddress((void**)&Ph, g_Ph);
    cudaGetSymbolAddress((void**)&AOh, g_AOh);

    constexpr int SM1_64 = STAGES * 2 * 16384;   // 96 KB (1-term, chunk 64)
    constexpr int SM2_32 = STAGES * 3 * 8192;    // 72 KB (2-term, chunk 32)
    constexpr int SM3_32 = STAGES * 4 * 8192;    // 96 KB (3-term, chunk 32)
    cudaFuncSetAttribute((const void*)mma_gemm<1, 2, 64>, cudaFuncAttributeMaxDynamicSharedMemorySize, SM1_64);
    cudaFuncSetAttribute((const void*)mma_gemm<1, 4, 64>, cudaFuncAttributeMaxDynamicSharedMemorySize, SM1_64);
    cudaFuncSetAttribute((const void*)mma_gemm<2, 3, 32>, cudaFuncAttributeMaxDynamicSharedMemorySize, SM2_32);
    cudaFuncSetAttribute((const void*)qkv_gemm, cudaFuncAttributeMaxDynamicSharedMemorySize, SM3_32);

    // 1) split inputs + weights into fp16 hi/lo (single launch)
    CvtArgs ca;
    ca.x[0] = (const float4*)query;  ca.h[0] = (uint2*)qh;  ca.l[0] = (uint2*)ql;
    ca.x[1] = (const float4*)keys;   ca.h[1] = (uint2*)kh;  ca.l[1] = (uint2*)kl;
    ca.x[2] = (const float4*)values; ca.h[2] = (uint2*)vh;  ca.l[2] = (uint2*)vl;
    ca.x[3] = (const float4*)Wq;     ca.h[3] = (uint2*)Wqh; ca.l[3] = (uint2*)Wql;
    ca.x[4] = (const float4*)Wk;     ca.h[4] = (uint2*)Wkh; ca.l[4] = (uint2*)Wkl;
    ca.x[5] = (const float4*)Wv;     ca.h[5] = (uint2*)Wvh; ca.l[5] = (uint2*)Wvl;
    ca.x[6] = (const float4*)Wo;     ca.h[6] = (uint2*)Woh; ca.l[6] = (uint2*)Wol;
    cvt_all<<<(CVT_TOT + 255) / 256, 256>>>(ca);

    const dim3 blk(256);
    const long long sQK = (long long)SEQ * EMB;
    const long long sE  = (long long)SEQ * SEQ;

    // 2) merged projections: z=0 Q (hi), z=1 K (hi), z=2 V (transposed hi)
    QKVArgs qa;
    qa.p[0] = { qh, ql, Wqh, Wql, Qph };
    qa.p[1] = { kh, kl, Wkh, Wkl, Kph };
    qa.p[2] = { vh, vl, Wvh, Wvl, VTh };
    qkv_gemm<<<dim3(EMB / 128, NTOK / 128, 3), blk, SM3_32>>>(qa);

    // 3) energy: per-batch [4096,4096] = Qph @ Kph^T, 1-term chunk64 -> scaled fp16
    mma_gemm<1, 2, 64><<<dim3(SEQ / 128, SEQ / 128, NB), blk, SM1_64>>>(
        Qph, nullptr, Kph, nullptr, nullptr, Eh, nullptr, EMB, SEQ, sQK, sQK, sE);

    // 4) mask + softmax -> attn fp16 (hi only)
    softmax_mask_kernel<<<NB * SEQ, 256>>>(Eh, mask, Ph);

    // 5) attn @ V: per-batch [4096,512] = Ph @ VTh^T, 1-term chunk64 (hi out)
    mma_gemm<1, 4, 64><<<dim3(EMB / 128, SEQ / 128, NB), blk, SM1_64>>>(
        Ph, nullptr, VTh, nullptr, nullptr, AOh, nullptr, SEQ, EMB, sE, sQK, sQK);

    // 6) output projection + bias, 2-term (fp32 out)
    mma_gemm<2, 3, 32><<<dim3(EMB / 128, NTOK / 128, 1), blk, SM2_32>>>(
        AOh, nullptr, Woh, Wol, out, nullptr, bo, EMB, EMB, 0, 0, 0);
}